// round 1
// baseline (speedup 1.0000x reference)
#include <cuda_runtime.h>
#include <math.h>

// Transformer block, fully fused: one CTA per batch element (B=4096).
// T=64, C=64, NH=4, HD=16. All activations live in shared memory.
// Phases: load x -> LN1 -> QKV gemm -> causal attention -> proj(+res)
//         -> LN2 -> FC gemm + exact GELU -> proj2(+res) -> store.

#define T_ 64
#define C_ 64
#define NH_ 4
#define HD_ 16
#define EPS_ 1e-5f

// smem layout (floats):
// xs   [64*64]   = 4096   residual stream
// bufB [64*64]   = 4096   LN output / attention output y
// bufA [64*256]  = 16384  qkv (64x192 used) / fc activation (64x256)
// pbuf [8*64]    = 512    per-warp softmax row buffer
#define SMEM_FLOATS (4096 + 4096 + 16384 + 512)
#define SMEM_BYTES  (SMEM_FLOATS * 4)

// ---------------------------------------------------------------------------
// Generic tiled GEMM: O[64][N] = A[64][K] @ W[K][N] + bias, A in smem,
// W in global (L2-resident), O in smem. 256 threads, 4x4 register tile.
// ACT: 0 = none, 1 = exact GELU.
// ---------------------------------------------------------------------------
template <int K, int N, int ACT>
__device__ __forceinline__ void gemm_smem(const float* __restrict__ A,
                                          const float* __restrict__ W,
                                          const float* __restrict__ bias,
                                          float* __restrict__ O, int tid) {
    const int ty = tid >> 4;        // 0..15
    const int tx = tid & 15;        // 0..15
    const int r0 = ty * 4;          // row base
    #pragma unroll
    for (int pass = 0; pass < N / 64; ++pass) {
        const int j0 = pass * 64 + tx * 4;
        const float4 bb = *(const float4*)(bias + j0);
        float acc[4][4];
        #pragma unroll
        for (int i = 0; i < 4; ++i) {
            acc[i][0] = bb.x; acc[i][1] = bb.y; acc[i][2] = bb.z; acc[i][3] = bb.w;
        }
        #pragma unroll 8
        for (int k = 0; k < K; ++k) {
            const float4 wv = __ldg((const float4*)(W + k * N + j0));
            #pragma unroll
            for (int i = 0; i < 4; ++i) {
                const float a = A[(r0 + i) * K + k];
                acc[i][0] = fmaf(a, wv.x, acc[i][0]);
                acc[i][1] = fmaf(a, wv.y, acc[i][1]);
                acc[i][2] = fmaf(a, wv.z, acc[i][2]);
                acc[i][3] = fmaf(a, wv.w, acc[i][3]);
            }
        }
        #pragma unroll
        for (int i = 0; i < 4; ++i) {
            float4 o;
            if (ACT == 1) {
                // exact GELU: 0.5*v*(1+erf(v/sqrt(2)))
                o.x = 0.5f * acc[i][0] * (1.0f + erff(acc[i][0] * 0.70710678118654752f));
                o.y = 0.5f * acc[i][1] * (1.0f + erff(acc[i][1] * 0.70710678118654752f));
                o.z = 0.5f * acc[i][2] * (1.0f + erff(acc[i][2] * 0.70710678118654752f));
                o.w = 0.5f * acc[i][3] * (1.0f + erff(acc[i][3] * 0.70710678118654752f));
            } else {
                o.x = acc[i][0]; o.y = acc[i][1]; o.z = acc[i][2]; o.w = acc[i][3];
            }
            *(float4*)(O + (r0 + i) * N + j0) = o;
        }
    }
}

// GEMM (K=64, N=64) with residual accumulation into xs (in place).
__device__ __forceinline__ void gemm_residual(const float* __restrict__ A,
                                              const float* __restrict__ W,
                                              const float* __restrict__ bias,
                                              float* __restrict__ xs, int tid) {
    const int ty = tid >> 4, tx = tid & 15;
    const int r0 = ty * 4, j0 = tx * 4;
    const float4 bb = *(const float4*)(bias + j0);
    float acc[4][4];
    #pragma unroll
    for (int i = 0; i < 4; ++i) {
        acc[i][0] = bb.x; acc[i][1] = bb.y; acc[i][2] = bb.z; acc[i][3] = bb.w;
    }
    #pragma unroll 8
    for (int k = 0; k < 64; ++k) {
        const float4 wv = __ldg((const float4*)(W + k * 64 + j0));
        #pragma unroll
        for (int i = 0; i < 4; ++i) {
            const float a = A[(r0 + i) * 64 + k];
            acc[i][0] = fmaf(a, wv.x, acc[i][0]);
            acc[i][1] = fmaf(a, wv.y, acc[i][1]);
            acc[i][2] = fmaf(a, wv.z, acc[i][2]);
            acc[i][3] = fmaf(a, wv.w, acc[i][3]);
        }
    }
    #pragma unroll
    for (int i = 0; i < 4; ++i) {
        float4 r = *(float4*)(xs + (r0 + i) * 64 + j0);
        r.x += acc[i][0]; r.y += acc[i][1]; r.z += acc[i][2]; r.w += acc[i][3];
        *(float4*)(xs + (r0 + i) * 64 + j0) = r;
    }
}

// Final GEMM (K=256, N=64): out_global = xs + A @ W + bias
__device__ __forceinline__ void gemm_final(const float* __restrict__ A,
                                           const float* __restrict__ W,
                                           const float* __restrict__ bias,
                                           const float* __restrict__ xs,
                                           float* __restrict__ og, int tid) {
    const int ty = tid >> 4, tx = tid & 15;
    const int r0 = ty * 4, j0 = tx * 4;
    const float4 bb = *(const float4*)(bias + j0);
    float acc[4][4];
    #pragma unroll
    for (int i = 0; i < 4; ++i) {
        acc[i][0] = bb.x; acc[i][1] = bb.y; acc[i][2] = bb.z; acc[i][3] = bb.w;
    }
    #pragma unroll 8
    for (int k = 0; k < 256; ++k) {
        const float4 wv = __ldg((const float4*)(W + k * 64 + j0));
        #pragma unroll
        for (int i = 0; i < 4; ++i) {
            const float a = A[(r0 + i) * 256 + k];
            acc[i][0] = fmaf(a, wv.x, acc[i][0]);
            acc[i][1] = fmaf(a, wv.y, acc[i][1]);
            acc[i][2] = fmaf(a, wv.z, acc[i][2]);
            acc[i][3] = fmaf(a, wv.w, acc[i][3]);
        }
    }
    #pragma unroll
    for (int i = 0; i < 4; ++i) {
        float4 r = *(const float4*)(xs + (r0 + i) * 64 + j0);
        r.x += acc[i][0]; r.y += acc[i][1]; r.z += acc[i][2]; r.w += acc[i][3];
        *(float4*)(og + (r0 + i) * 64 + j0) = r;
    }
}

// LayerNorm: 4 threads per row (each covers 16 cols), quad shuffle reduce.
__device__ __forceinline__ void layernorm(const float* __restrict__ xs,
                                          const float* __restrict__ g,
                                          const float* __restrict__ b,
                                          float* __restrict__ h, int tid) {
    const int row = tid >> 2;        // 0..63
    const int part = tid & 3;        // 0..3
    const int c0 = part * 16;
    float v[16];
    float s = 0.f, s2 = 0.f;
    #pragma unroll
    for (int i = 0; i < 16; ++i) {
        v[i] = xs[row * 64 + c0 + i];
        s += v[i];
        s2 += v[i] * v[i];
    }
    // reduce within aligned quad (xor 1, xor 2 stay within groups of 4 lanes)
    s  += __shfl_xor_sync(0xffffffffu, s, 1);
    s2 += __shfl_xor_sync(0xffffffffu, s2, 1);
    s  += __shfl_xor_sync(0xffffffffu, s, 2);
    s2 += __shfl_xor_sync(0xffffffffu, s2, 2);
    const float mu = s * (1.0f / 64.0f);
    const float var = s2 * (1.0f / 64.0f) - mu * mu;
    const float rstd = rsqrtf(var + EPS_);
    #pragma unroll
    for (int i = 0; i < 16; ++i) {
        h[row * 64 + c0 + i] = (v[i] - mu) * rstd * g[c0 + i] + b[c0 + i];
    }
}

__global__ __launch_bounds__(256, 2) void block_fused_kernel(
    const float* __restrict__ x,
    const float* __restrict__ ln1_g, const float* __restrict__ ln1_b,
    const float* __restrict__ qkv_w, const float* __restrict__ qkv_b,
    const float* __restrict__ aproj_w, const float* __restrict__ aproj_b,
    const float* __restrict__ ln2_g, const float* __restrict__ ln2_b,
    const float* __restrict__ fc_w, const float* __restrict__ fc_b,
    const float* __restrict__ mproj_w, const float* __restrict__ mproj_b,
    float* __restrict__ out) {
    extern __shared__ float smem[];
    float* xs   = smem;                 // 4096
    float* bufB = smem + 4096;          // 4096
    float* bufA = smem + 8192;          // 16384
    float* pbuf = smem + 8192 + 16384;  // 512

    const int tid = threadIdx.x;
    const size_t base = (size_t)blockIdx.x * (T_ * C_);
    const float* xg = x + base;
    float* og = out + base;

    // ---- load x tile ----
    {
        const float4* src = (const float4*)xg;
        float4* dst = (float4*)xs;
        #pragma unroll
        for (int i = tid; i < T_ * C_ / 4; i += 256) dst[i] = src[i];
    }
    __syncthreads();

    // ---- LN1 ----
    layernorm(xs, ln1_g, ln1_b, bufB, tid);
    __syncthreads();

    // ---- QKV GEMM: bufB[64x64] @ qkv_w[64x192] -> bufA[64x192] ----
    gemm_smem<64, 192, 0>(bufB, qkv_w, qkv_b, bufA, tid);
    __syncthreads();

    // ---- causal attention: qkv(bufA) -> y(bufB) ----
    {
        const int w = tid >> 5;           // warp 0..7
        const int lane = tid & 31;
        const int head = w >> 1;          // 2 warps per head
        const int rbase = (w & 1) * 32;   // rows handled by this warp
        float* pw = pbuf + w * 64;
        const int j0 = lane, j1 = lane + 32;
        const float* krow0 = bufA + j0 * 192 + 64 + head * HD_;
        const float* krow1 = bufA + j1 * 192 + 64 + head * HD_;
        const int d = lane & 15, seg = lane >> 4;
        const float* vcol = bufA + 128 + head * HD_ + d;

        for (int r = 0; r < 32; ++r) {
            const int i = rbase + r;
            const float* qrow = bufA + i * 192 + head * HD_;
            float s0 = 0.f, s1 = 0.f;
            #pragma unroll
            for (int dd = 0; dd < HD_; ++dd) {
                const float qd = qrow[dd];
                s0 = fmaf(qd, krow0[dd], s0);
                s1 = fmaf(qd, krow1[dd], s1);
            }
            s0 = (j0 <= i) ? s0 * 0.25f : -INFINITY;
            s1 = (j1 <= i) ? s1 * 0.25f : -INFINITY;
            float m = fmaxf(s0, s1);
            #pragma unroll
            for (int o = 16; o; o >>= 1)
                m = fmaxf(m, __shfl_xor_sync(0xffffffffu, m, o));
            const float p0 = (j0 <= i) ? __expf(s0 - m) : 0.f;
            const float p1 = (j1 <= i) ? __expf(s1 - m) : 0.f;
            float den = p0 + p1;
            #pragma unroll
            for (int o = 16; o; o >>= 1)
                den += __shfl_xor_sync(0xffffffffu, den, o);
            const float inv = 1.0f / den;
            pw[lane] = p0;
            pw[lane + 32] = p1;
            __syncwarp();
            // y[i][head*16+d] = sum_j p[j] * v[j][d]
            float acc = 0.f;
            const float* pseg = pw + seg * 32;
            const float* vseg = vcol + seg * 32 * 192;
            #pragma unroll
            for (int jj = 0; jj < 32; ++jj)
                acc = fmaf(pseg[jj], vseg[jj * 192], acc);
            acc += __shfl_xor_sync(0xffffffffu, acc, 16);
            if (lane < 16) bufB[i * 64 + head * HD_ + d] = acc * inv;
            __syncwarp();
        }
    }
    __syncthreads();

    // ---- attention proj + residual: xs += y @ aproj_w + b ----
    gemm_residual(bufB, aproj_w, aproj_b, xs, tid);
    __syncthreads();

    // ---- LN2 ----
    layernorm(xs, ln2_g, ln2_b, bufB, tid);
    __syncthreads();

    // ---- FC GEMM + exact GELU: bufB @ fc_w[64x256] -> bufA ----
    gemm_smem<64, 256, 1>(bufB, fc_w, fc_b, bufA, tid);
    __syncthreads();

    // ---- MLP proj + residual -> global out ----
    gemm_final(bufA, mproj_w, mproj_b, xs, og, tid);
}

extern "C" void kernel_launch(void* const* d_in, const int* in_sizes, int n_in,
                              void* d_out, int out_size) {
    const float* x       = (const float*)d_in[0];
    const float* ln1_g   = (const float*)d_in[1];
    const float* ln1_b   = (const float*)d_in[2];
    const float* qkv_w   = (const float*)d_in[3];
    const float* qkv_b   = (const float*)d_in[4];
    const float* aproj_w = (const float*)d_in[5];
    const float* aproj_b = (const float*)d_in[6];
    const float* ln2_g   = (const float*)d_in[7];
    const float* ln2_b   = (const float*)d_in[8];
    const float* fc_w    = (const float*)d_in[9];
    const float* fc_b    = (const float*)d_in[10];
    const float* mproj_w = (const float*)d_in[11];
    const float* mproj_b = (const float*)d_in[12];
    float* out = (float*)d_out;

    const int B = in_sizes[0] / (T_ * C_);  // 4096

    static int configured = 0;
    if (!configured) {
        cudaFuncSetAttribute(block_fused_kernel,
                             cudaFuncAttributeMaxDynamicSharedMemorySize,
                             SMEM_BYTES);
        configured = 1;
    }

    block_fused_kernel<<<B, 256, SMEM_BYTES>>>(
        x, ln1_g, ln1_b, qkv_w, qkv_b, aproj_w, aproj_b,
        ln2_g, ln2_b, fc_w, fc_b, mproj_w, mproj_b, out);
}

// round 2
// speedup vs baseline: 1.6228x; 1.6228x over previous
#include <cuda_runtime.h>
#include <math.h>

// Fused transformer block: one CTA per batch element (B=4096).
// T=64, C=64, NH=4, HD=16. All activations in shared memory.
// R2: vectorized GEMM inner loops (LDS.128/LDG.128, k-step 4) to cut L1tex
// traffic 2.5x; MLP split into two 128-col passes; 3 CTAs/SM target.

#define T_ 64
#define C_ 64
#define HD_ 16
#define EPS_ 1e-5f

// smem floats: xs 4096 | bufB 4096 | qkv/bufA 12288 | pbuf 512
#define SMEM_FLOATS (4096 + 4096 + 12288 + 512)
#define SMEM_BYTES  (SMEM_FLOATS * 4)

__device__ __forceinline__ void accum_k(const float* __restrict__ A, int lda,
                                        const float* __restrict__ W, int ldw,
                                        int K, int r0, int j0,
                                        float acc[4][4]) {
    #pragma unroll 4
    for (int k = 0; k < K; k += 4) {
        const float4 w0 = __ldg((const float4*)(W + (k + 0) * ldw + j0));
        const float4 w1 = __ldg((const float4*)(W + (k + 1) * ldw + j0));
        const float4 w2 = __ldg((const float4*)(W + (k + 2) * ldw + j0));
        const float4 w3 = __ldg((const float4*)(W + (k + 3) * ldw + j0));
        #pragma unroll
        for (int i = 0; i < 4; ++i) {
            const float4 a = *(const float4*)(A + (r0 + i) * lda + k);
            acc[i][0] = fmaf(a.x, w0.x, acc[i][0]);
            acc[i][1] = fmaf(a.x, w0.y, acc[i][1]);
            acc[i][2] = fmaf(a.x, w0.z, acc[i][2]);
            acc[i][3] = fmaf(a.x, w0.w, acc[i][3]);
            acc[i][0] = fmaf(a.y, w1.x, acc[i][0]);
            acc[i][1] = fmaf(a.y, w1.y, acc[i][1]);
            acc[i][2] = fmaf(a.y, w1.z, acc[i][2]);
            acc[i][3] = fmaf(a.y, w1.w, acc[i][3]);
            acc[i][0] = fmaf(a.z, w2.x, acc[i][0]);
            acc[i][1] = fmaf(a.z, w2.y, acc[i][1]);
            acc[i][2] = fmaf(a.z, w2.z, acc[i][2]);
            acc[i][3] = fmaf(a.z, w2.w, acc[i][3]);
            acc[i][0] = fmaf(a.w, w3.x, acc[i][0]);
            acc[i][1] = fmaf(a.w, w3.y, acc[i][1]);
            acc[i][2] = fmaf(a.w, w3.z, acc[i][2]);
            acc[i][3] = fmaf(a.w, w3.w, acc[i][3]);
        }
    }
}

template <int ACT>
__device__ __forceinline__ void gemm_tile64(const float* __restrict__ A, int lda,
                                            const float* __restrict__ W, int ldw,
                                            const float* __restrict__ bias,
                                            float* __restrict__ O, int ldo,
                                            int K, int tid) {
    const int r0 = (tid >> 4) * 4;
    const int j0 = (tid & 15) * 4;
    const float4 bb = *(const float4*)(bias + j0);
    float acc[4][4];
    #pragma unroll
    for (int i = 0; i < 4; ++i) {
        acc[i][0] = bb.x; acc[i][1] = bb.y; acc[i][2] = bb.z; acc[i][3] = bb.w;
    }
    accum_k(A, lda, W, ldw, K, r0, j0, acc);
    #pragma unroll
    for (int i = 0; i < 4; ++i) {
        float4 o;
        if (ACT == 1) {
            o.x = 0.5f * acc[i][0] * (1.0f + erff(acc[i][0] * 0.70710678118654752f));
            o.y = 0.5f * acc[i][1] * (1.0f + erff(acc[i][1] * 0.70710678118654752f));
            o.z = 0.5f * acc[i][2] * (1.0f + erff(acc[i][2] * 0.70710678118654752f));
            o.w = 0.5f * acc[i][3] * (1.0f + erff(acc[i][3] * 0.70710678118654752f));
        } else {
            o.x = acc[i][0]; o.y = acc[i][1]; o.z = acc[i][2]; o.w = acc[i][3];
        }
        *(float4*)(O + (r0 + i) * ldo + j0) = o;
    }
}

__device__ __forceinline__ void layernorm(const float* __restrict__ xs,
                                          const float* __restrict__ g,
                                          const float* __restrict__ b,
                                          float* __restrict__ h, int tid) {
    const int row = tid >> 2;
    const int c0 = (tid & 3) * 16;
    float v[16];
    float s = 0.f, s2 = 0.f;
    #pragma unroll
    for (int i = 0; i < 16; ++i) {
        v[i] = xs[row * 64 + c0 + i];
        s += v[i];
        s2 += v[i] * v[i];
    }
    s  += __shfl_xor_sync(0xffffffffu, s, 1);
    s2 += __shfl_xor_sync(0xffffffffu, s2, 1);
    s  += __shfl_xor_sync(0xffffffffu, s, 2);
    s2 += __shfl_xor_sync(0xffffffffu, s2, 2);
    const float mu = s * (1.0f / 64.0f);
    const float var = s2 * (1.0f / 64.0f) - mu * mu;
    const float rstd = rsqrtf(var + EPS_);
    #pragma unroll
    for (int i = 0; i < 16; ++i)
        h[row * 64 + c0 + i] = (v[i] - mu) * rstd * g[c0 + i] + b[c0 + i];
}

__global__ __launch_bounds__(256, 3) void block_fused_kernel(
    const float* __restrict__ x,
    const float* __restrict__ ln1_g, const float* __restrict__ ln1_b,
    const float* __restrict__ qkv_w, const float* __restrict__ qkv_b,
    const float* __restrict__ aproj_w, const float* __restrict__ aproj_b,
    const float* __restrict__ ln2_g, const float* __restrict__ ln2_b,
    const float* __restrict__ fc_w, const float* __restrict__ fc_b,
    const float* __restrict__ mproj_w, const float* __restrict__ mproj_b,
    float* __restrict__ out) {
    extern __shared__ float smem[];
    float* xs   = smem;            // 4096
    float* bufB = smem + 4096;     // 4096
    float* bufA = smem + 8192;     // 12288: qkv 64x192 / fc chunk 64x128
    float* pbuf = smem + 20480;    // 512 (after full qkv region)

    const int tid = threadIdx.x;
    const size_t base = (size_t)blockIdx.x * (T_ * C_);
    const float* xg = x + base;
    float* og = out + base;

    const int r0 = (tid >> 4) * 4;
    const int j0 = (tid & 15) * 4;

    // ---- load x tile ----
    {
        const float4* src = (const float4*)xg;
        float4* dst = (float4*)xs;
        #pragma unroll
        for (int i = tid; i < T_ * C_ / 4; i += 256) dst[i] = src[i];
    }
    __syncthreads();

    // ---- LN1 -> bufB ----
    layernorm(xs, ln1_g, ln1_b, bufB, tid);
    __syncthreads();

    // ---- QKV GEMM ----
    #pragma unroll
    for (int c = 0; c < 3; ++c)
        gemm_tile64<0>(bufB, 64, qkv_w + c * 64, 192, qkv_b + c * 64,
                       bufA + c * 64, 192, 64, tid);
    __syncthreads();

    // ---- causal attention: bufA(qkv) -> y(bufB) ----
    {
        const int w = tid >> 5;
        const int lane = tid & 31;
        const int head = w >> 1;
        const int rbase = (w & 1) * 32;
        float* pw = pbuf + w * 64;
        const int jj0 = lane, jj1 = lane + 32;
        const float* krow0 = bufA + jj0 * 192 + 64 + head * HD_;
        const float* krow1 = bufA + jj1 * 192 + 64 + head * HD_;
        const int d = lane & 15, seg = lane >> 4;
        const float* vcol = bufA + 128 + head * HD_ + d;

        for (int r = 0; r < 32; ++r) {
            const int i = rbase + r;
            const float* qrow = bufA + i * 192 + head * HD_;
            float s0 = 0.f, s1 = 0.f;
            #pragma unroll
            for (int dd = 0; dd < HD_; ++dd) {
                const float qd = qrow[dd];
                s0 = fmaf(qd, krow0[dd], s0);
                s1 = fmaf(qd, krow1[dd], s1);
            }
            s0 = (jj0 <= i) ? s0 * 0.25f : -INFINITY;
            s1 = (jj1 <= i) ? s1 * 0.25f : -INFINITY;
            float m = fmaxf(s0, s1);
            #pragma unroll
            for (int o = 16; o; o >>= 1)
                m = fmaxf(m, __shfl_xor_sync(0xffffffffu, m, o));
            const float p0 = (jj0 <= i) ? __expf(s0 - m) : 0.f;
            const float p1 = (jj1 <= i) ? __expf(s1 - m) : 0.f;
            float den = p0 + p1;
            #pragma unroll
            for (int o = 16; o; o >>= 1)
                den += __shfl_xor_sync(0xffffffffu, den, o);
            const float inv = 1.0f / den;
            pw[lane] = p0;
            pw[lane + 32] = p1;
            __syncwarp();
            float acc = 0.f;
            const float* pseg = pw + seg * 32;
            const float* vseg = vcol + seg * 32 * 192;
            #pragma unroll
            for (int k = 0; k < 32; ++k)
                acc = fmaf(pseg[k], vseg[k * 192], acc);
            acc += __shfl_xor_sync(0xffffffffu, acc, 16);
            if (lane < 16) bufB[i * 64 + head * HD_ + d] = acc * inv;
            __syncwarp();
        }
    }
    __syncthreads();

    // ---- attention proj + residual ----
    {
        const float4 bb = *(const float4*)(aproj_b + j0);
        float acc[4][4];
        #pragma unroll
        for (int i = 0; i < 4; ++i) {
            acc[i][0] = bb.x; acc[i][1] = bb.y; acc[i][2] = bb.z; acc[i][3] = bb.w;
        }
        accum_k(bufB, 64, aproj_w, 64, 64, r0, j0, acc);
        __syncthreads();
        #pragma unroll
        for (int i = 0; i < 4; ++i) {
            float4 rv = *(float4*)(xs + (r0 + i) * 64 + j0);
            rv.x += acc[i][0]; rv.y += acc[i][1]; rv.z += acc[i][2]; rv.w += acc[i][3];
            *(float4*)(xs + (r0 + i) * 64 + j0) = rv;
        }
    }
    __syncthreads();

    // ---- LN2 -> bufB ----
    layernorm(xs, ln2_g, ln2_b, bufB, tid);
    __syncthreads();

    // ---- fused MLP: two 128-col passes, proj accumulator in registers ----
    float accO[4][4];
    {
        const float4 bb = *(const float4*)(mproj_b + j0);
        #pragma unroll
        for (int i = 0; i < 4; ++i) {
            const float4 rv = *(const float4*)(xs + (r0 + i) * 64 + j0);
            accO[i][0] = bb.x + rv.x; accO[i][1] = bb.y + rv.y;
            accO[i][2] = bb.z + rv.z; accO[i][3] = bb.w + rv.w;
        }
    }
    #pragma unroll
    for (int p = 0; p < 2; ++p) {
        #pragma unroll
        for (int c = 0; c < 2; ++c)
            gemm_tile64<1>(bufB, 64, fc_w + p * 128 + c * 64, 256,
                           fc_b + p * 128 + c * 64, bufA + c * 64, 128, 64, tid);
        __syncthreads();
        accum_k(bufA, 128, mproj_w + p * 128 * 64, 64, 128, r0, j0, accO);
        __syncthreads();
    }
    #pragma unroll
    for (int i = 0; i < 4; ++i) {
        float4 o;
        o.x = accO[i][0]; o.y = accO[i][1]; o.z = accO[i][2]; o.w = accO[i][3];
        *(float4*)(og + (r0 + i) * 64 + j0) = o;
    }
}

extern "C" void kernel_launch(void* const* d_in, const int* in_sizes, int n_in,
                              void* d_out, int out_size) {
    const float* x       = (const float*)d_in[0];
    const float* ln1_g   = (const float*)d_in[1];
    const float* ln1_b   = (const float*)d_in[2];
    const float* qkv_w   = (const float*)d_in[3];
    const float* qkv_b   = (const float*)d_in[4];
    const float* aproj_w = (const float*)d_in[5];
    const float* aproj_b = (const float*)d_in[6];
    const float* ln2_g   = (const float*)d_in[7];
    const float* ln2_b   = (const float*)d_in[8];
    const float* fc_w    = (const float*)d_in[9];
    const float* fc_b    = (const float*)d_in[10];
    const float* mproj_w = (const float*)d_in[11];
    const float* mproj_b = (const float*)d_in[12];
    float* out = (float*)d_out;

    const int B = in_sizes[0] / (T_ * C_);

    cudaFuncSetAttribute(block_fused_kernel,
                         cudaFuncAttributeMaxDynamicSharedMemorySize,
                         SMEM_BYTES);

    block_fused_kernel<<<B, 256, SMEM_BYTES>>>(
        x, ln1_g, ln1_b, qkv_w, qkv_b, aproj_w, aproj_b,
        ln2_g, ln2_b, fc_w, fc_b, mproj_w, mproj_b, out);
}

// round 3
// speedup vs baseline: 12.7114x; 7.8328x over previous
#include <cuda_runtime.h>
#include <cuda_bf16.h>
#include <math.h>
#include <stdint.h>

// Fused transformer block on tensor cores (bf16 mma.sync, fp32 accum).
// One CTA (256 thr = 8 warps) per batch element. B=4096, T=64, C=64, H=4, d=16.

#define T_ 64
#define C_ 64
#define EPS_ 1e-5f

// ---------------- bf16 weight mirrors (filled by prologue kernel) -----------
__device__ __nv_bfloat16 g_wqkv[64 * 192];
__device__ __nv_bfloat16 g_waproj[64 * 64];
__device__ __nv_bfloat16 g_wfc[64 * 256];
__device__ __nv_bfloat16 g_wmproj[256 * 64];

__global__ void convert_weights_kernel(const float* __restrict__ qkv_w,
                                       const float* __restrict__ aproj_w,
                                       const float* __restrict__ fc_w,
                                       const float* __restrict__ mproj_w) {
    const int i = blockIdx.x * blockDim.x + threadIdx.x;
    if (i < 64 * 192) g_wqkv[i]   = __float2bfloat16(qkv_w[i]);
    if (i < 64 * 64)  g_waproj[i] = __float2bfloat16(aproj_w[i]);
    if (i < 64 * 256) g_wfc[i]    = __float2bfloat16(fc_w[i]);
    if (i < 256 * 64) g_wmproj[i] = __float2bfloat16(mproj_w[i]);
}

// ---------------- mma / ldmatrix helpers ------------------------------------
__device__ __forceinline__ uint32_t smem_u32(const void* p) {
    return (uint32_t)__cvta_generic_to_shared(p);
}
__device__ __forceinline__ void ldsm_x4(uint32_t a, uint32_t& r0, uint32_t& r1,
                                        uint32_t& r2, uint32_t& r3) {
    asm volatile("ldmatrix.sync.aligned.m8n8.x4.shared.b16 {%0,%1,%2,%3}, [%4];\n"
                 : "=r"(r0), "=r"(r1), "=r"(r2), "=r"(r3) : "r"(a));
}
__device__ __forceinline__ void ldsm_x2(uint32_t a, uint32_t& r0, uint32_t& r1) {
    asm volatile("ldmatrix.sync.aligned.m8n8.x2.shared.b16 {%0,%1}, [%2];\n"
                 : "=r"(r0), "=r"(r1) : "r"(a));
}
__device__ __forceinline__ void ldsm_x2t(uint32_t a, uint32_t& r0, uint32_t& r1) {
    asm volatile("ldmatrix.sync.aligned.m8n8.x2.trans.shared.b16 {%0,%1}, [%2];\n"
                 : "=r"(r0), "=r"(r1) : "r"(a));
}
__device__ __forceinline__ void mma16816(float& d0, float& d1, float& d2, float& d3,
                                         uint32_t a0, uint32_t a1, uint32_t a2,
                                         uint32_t a3, uint32_t b0, uint32_t b1) {
    asm volatile(
        "mma.sync.aligned.m16n8k16.row.col.f32.bf16.bf16.f32 "
        "{%0,%1,%2,%3},{%4,%5,%6,%7},{%8,%9},{%0,%1,%2,%3};\n"
        : "+f"(d0), "+f"(d1), "+f"(d2), "+f"(d3)
        : "r"(a0), "r"(a1), "r"(a2), "r"(a3), "r"(b0), "r"(b1));
}
__device__ __forceinline__ uint32_t packbf(float x, float y) {
    __nv_bfloat162 h = __floats2bfloat162_rn(x, y);
    return *(uint32_t*)&h;
}

// Dense tile mma: D[NF][4] += A[m0..m0+15, 0..KS*16) @ B[0..KS*16, n0 + j*8)
// A row-major (a_ld halves), B row-major [k][n] (b_ld halves), both bf16 smem.
template <int KS, int NF>
__device__ __forceinline__ void mma_tile(uint32_t a_base, int a_ld,
                                         uint32_t b_base, int b_ld,
                                         int m0, int n0, float d[NF][4], int lane) {
    const int ar = m0 + (lane & 15);
    const int ac = (lane >> 4) << 3;
    const int br = (lane & 15);
    #pragma unroll
    for (int kk = 0; kk < KS; ++kk) {
        uint32_t a0, a1, a2, a3;
        ldsm_x4(a_base + (uint32_t)((ar * a_ld + kk * 16 + ac) * 2), a0, a1, a2, a3);
        #pragma unroll
        for (int j = 0; j < NF; ++j) {
            uint32_t b0, b1;
            ldsm_x2t(b_base + (uint32_t)(((kk * 16 + br) * b_ld + n0 + j * 8) * 2), b0, b1);
            mma16816(d[j][0], d[j][1], d[j][2], d[j][3], a0, a1, a2, a3, b0, b1);
        }
    }
}

// Copy bf16 global -> bf16 smem with padded stride, 16B chunks.
__device__ __forceinline__ void copy_w(const __nv_bfloat16* __restrict__ src, int src_ld,
                                       __nv_bfloat16* dst, int dst_ld,
                                       int rows, int cols, int tid) {
    const int c8 = cols >> 3;
    for (int i = tid; i < rows * c8; i += 256) {
        const int r = i / c8;
        const int c = (i - r * c8) << 3;
        *(uint4*)(dst + r * dst_ld + c) = *(const uint4*)(src + r * src_ld + c);
    }
}

// LayerNorm fp32 xs -> bf16 h (stride 72). 4 threads/row.
__device__ __forceinline__ void layernorm_bf16(const float* __restrict__ xs,
                                               const float* __restrict__ g,
                                               const float* __restrict__ b,
                                               __nv_bfloat16* __restrict__ h, int tid) {
    const int row = tid >> 2;
    const int c0 = (tid & 3) * 16;
    float v[16];
    float s = 0.f, s2 = 0.f;
    #pragma unroll
    for (int i = 0; i < 16; ++i) {
        v[i] = xs[row * 64 + c0 + i];
        s += v[i];
        s2 += v[i] * v[i];
    }
    s  += __shfl_xor_sync(0xffffffffu, s, 1);
    s2 += __shfl_xor_sync(0xffffffffu, s2, 1);
    s  += __shfl_xor_sync(0xffffffffu, s, 2);
    s2 += __shfl_xor_sync(0xffffffffu, s2, 2);
    const float mu = s * (1.0f / 64.0f);
    const float var = s2 * (1.0f / 64.0f) - mu * mu;
    const float rstd = rsqrtf(var + EPS_);
    #pragma unroll
    for (int i = 0; i < 8; ++i) {
        const float h0 = (v[2 * i] - mu) * rstd * g[c0 + 2 * i] + b[c0 + 2 * i];
        const float h1 = (v[2 * i + 1] - mu) * rstd * g[c0 + 2 * i + 1] + b[c0 + 2 * i + 1];
        *(uint32_t*)(h + row * 72 + c0 + 2 * i) = packbf(h0, h1);
    }
}

// smem layout (bytes): xs fp32 16384 | hb bf16 64x72 9216 | qkvs bf16 64x200 25600
//                      | wb bf16 (<=128x72 or 64x136) 18432   => total 69632
#define OFF_XS 0
#define OFF_HB 16384
#define OFF_QKV 25600
#define OFF_WB 51200
#define SMEM_BYTES 69632

__global__ __launch_bounds__(256, 3) void block_tc_kernel(
    const float* __restrict__ x,
    const float* __restrict__ ln1_g, const float* __restrict__ ln1_b,
    const float* __restrict__ qkv_b,
    const float* __restrict__ aproj_b,
    const float* __restrict__ ln2_g, const float* __restrict__ ln2_b,
    const float* __restrict__ fc_b,
    const float* __restrict__ mproj_b,
    float* __restrict__ out) {
    extern __shared__ char smem[];
    float* xs = (float*)(smem + OFF_XS);
    __nv_bfloat16* hb = (__nv_bfloat16*)(smem + OFF_HB);      // stride 72 (also y)
    __nv_bfloat16* qkvs = (__nv_bfloat16*)(smem + OFF_QKV);   // stride 200 (also fcact 136)
    __nv_bfloat16* wb = (__nv_bfloat16*)(smem + OFF_WB);      // stride 72 / 136
    const uint32_t hb_a = smem_u32(hb);
    const uint32_t qkv_a = smem_u32(qkvs);
    const uint32_t wb_a = smem_u32(wb);

    const int tid = threadIdx.x;
    const int wid = tid >> 5;
    const int lane = tid & 31;
    const int g = lane >> 2;
    const int t = lane & 3;
    const int wm = wid & 3;       // m-tile 0..3 (rows wm*16..+15)
    const int wn = wid >> 2;      // n-half 0..1
    const int r0 = wm * 16 + g;
    const int r1 = r0 + 8;

    const size_t base = (size_t)blockIdx.x * (T_ * C_);
    const float* xg = x + base;
    float* og = out + base;

    // ---- load x ----
    {
        const float4* src = (const float4*)xg;
        float4* dst = (float4*)xs;
        #pragma unroll
        for (int i = tid; i < T_ * C_ / 4; i += 256) dst[i] = src[i];
    }
    __syncthreads();

    // ---- LN1 -> hb ----
    layernorm_bf16(xs, ln1_g, ln1_b, hb, tid);
    __syncthreads();

    // ---- QKV: 3 chunks of 64 cols ----
    #pragma unroll
    for (int c = 0; c < 3; ++c) {
        copy_w(g_wqkv + c * 64, 192, wb, 72, 64, 64, tid);
        __syncthreads();
        float d[4][4];
        const int nb = wn * 32;
        #pragma unroll
        for (int j = 0; j < 4; ++j) {
            const int col = c * 64 + nb + j * 8 + t * 2;
            d[j][0] = d[j][2] = __ldg(qkv_b + col);
            d[j][1] = d[j][3] = __ldg(qkv_b + col + 1);
        }
        mma_tile<4, 4>(hb_a, 72, wb_a, 72, wm * 16, nb, d, lane);
        #pragma unroll
        for (int j = 0; j < 4; ++j) {
            const int col = c * 64 + nb + j * 8 + t * 2;
            *(uint32_t*)(qkvs + r0 * 200 + col) = packbf(d[j][0], d[j][1]);
            *(uint32_t*)(qkvs + r1 * 200 + col) = packbf(d[j][2], d[j][3]);
        }
        __syncthreads();
    }

    // ---- attention (tensor cores, register softmax) ----
    {
        const int h = wid >> 1;          // head
        const int half = wid & 1;        // row half
        #pragma unroll
        for (int mt = 0; mt < 2; ++mt) {
            const int rowbase = half * 32 + mt * 16;
            // Q fragment (k = 16 = head dim)
            uint32_t qa0, qa1, qa2, qa3;
            {
                const int r = rowbase + (lane & 15);
                const int cq = h * 16 + ((lane >> 4) << 3);
                ldsm_x4(qkv_a + (uint32_t)((r * 200 + cq) * 2), qa0, qa1, qa2, qa3);
            }
            // S = Q K^T (8 n-frags over 64 keys)
            float s[8][4];
            #pragma unroll
            for (int j = 0; j < 8; ++j) {
                uint32_t b0, b1;
                const int kr = j * 8 + (lane & 7);
                const int kc = 64 + h * 16 + (lane & 8);
                ldsm_x2(qkv_a + (uint32_t)((kr * 200 + kc) * 2), b0, b1);
                s[j][0] = s[j][1] = s[j][2] = s[j][3] = 0.f;
                mma16816(s[j][0], s[j][1], s[j][2], s[j][3], qa0, qa1, qa2, qa3, b0, b1);
            }
            // mask + scale + row max
            const int rA = rowbase + g, rB = rA + 8;
            float mA = -1e30f, mB = -1e30f;
            #pragma unroll
            for (int j = 0; j < 8; ++j) {
                #pragma unroll
                for (int e = 0; e < 2; ++e) {
                    const int col = j * 8 + t * 2 + e;
                    s[j][e]     = (col <= rA) ? s[j][e] * 0.25f     : -1e30f;
                    s[j][2 + e] = (col <= rB) ? s[j][2 + e] * 0.25f : -1e30f;
                    mA = fmaxf(mA, s[j][e]);
                    mB = fmaxf(mB, s[j][2 + e]);
                }
            }
            mA = fmaxf(mA, __shfl_xor_sync(0xffffffffu, mA, 1));
            mA = fmaxf(mA, __shfl_xor_sync(0xffffffffu, mA, 2));
            mB = fmaxf(mB, __shfl_xor_sync(0xffffffffu, mB, 1));
            mB = fmaxf(mB, __shfl_xor_sync(0xffffffffu, mB, 2));
            float sA = 0.f, sB = 0.f;
            #pragma unroll
            for (int j = 0; j < 8; ++j) {
                #pragma unroll
                for (int e = 0; e < 2; ++e) {
                    s[j][e] = __expf(s[j][e] - mA);
                    s[j][2 + e] = __expf(s[j][2 + e] - mB);
                    sA += s[j][e];
                    sB += s[j][2 + e];
                }
            }
            sA += __shfl_xor_sync(0xffffffffu, sA, 1);
            sA += __shfl_xor_sync(0xffffffffu, sA, 2);
            sB += __shfl_xor_sync(0xffffffffu, sB, 1);
            sB += __shfl_xor_sync(0xffffffffu, sB, 2);
            const float invA = 1.0f / sA, invB = 1.0f / sB;
            // y = P V  (P repacked from accumulators into A fragments)
            float y0[4] = {0.f, 0.f, 0.f, 0.f};
            float y1[4] = {0.f, 0.f, 0.f, 0.f};
            #pragma unroll
            for (int kk = 0; kk < 4; ++kk) {
                const uint32_t pa0 = packbf(s[2 * kk][0] * invA, s[2 * kk][1] * invA);
                const uint32_t pa1 = packbf(s[2 * kk][2] * invB, s[2 * kk][3] * invB);
                const uint32_t pa2 = packbf(s[2 * kk + 1][0] * invA, s[2 * kk + 1][1] * invA);
                const uint32_t pa3 = packbf(s[2 * kk + 1][2] * invB, s[2 * kk + 1][3] * invB);
                const int vr = kk * 16 + (lane & 15);
                uint32_t b0, b1;
                ldsm_x2t(qkv_a + (uint32_t)((vr * 200 + 128 + h * 16) * 2), b0, b1);
                mma16816(y0[0], y0[1], y0[2], y0[3], pa0, pa1, pa2, pa3, b0, b1);
                ldsm_x2t(qkv_a + (uint32_t)((vr * 200 + 128 + h * 16 + 8) * 2), b0, b1);
                mma16816(y1[0], y1[1], y1[2], y1[3], pa0, pa1, pa2, pa3, b0, b1);
            }
            // store y (bf16) into hb (reused as y buffer)
            const int cy = h * 16 + t * 2;
            *(uint32_t*)(hb + (rowbase + g) * 72 + cy)     = packbf(y0[0], y0[1]);
            *(uint32_t*)(hb + (rowbase + g + 8) * 72 + cy) = packbf(y0[2], y0[3]);
            *(uint32_t*)(hb + (rowbase + g) * 72 + cy + 8)     = packbf(y1[0], y1[1]);
            *(uint32_t*)(hb + (rowbase + g + 8) * 72 + cy + 8) = packbf(y1[2], y1[3]);
        }
    }
    __syncthreads();

    // ---- attention proj + residual into xs ----
    copy_w(g_waproj, 64, wb, 72, 64, 64, tid);
    __syncthreads();
    {
        float d[4][4];
        const int nb = wn * 32;
        #pragma unroll
        for (int j = 0; j < 4; ++j) {
            const int col = nb + j * 8 + t * 2;
            d[j][0] = d[j][2] = __ldg(aproj_b + col);
            d[j][1] = d[j][3] = __ldg(aproj_b + col + 1);
        }
        mma_tile<4, 4>(hb_a, 72, wb_a, 72, wm * 16, nb, d, lane);
        #pragma unroll
        for (int j = 0; j < 4; ++j) {
            const int col = nb + j * 8 + t * 2;
            float2 v0 = *(float2*)(xs + r0 * 64 + col);
            float2 v1 = *(float2*)(xs + r1 * 64 + col);
            v0.x += d[j][0]; v0.y += d[j][1];
            v1.x += d[j][2]; v1.y += d[j][3];
            *(float2*)(xs + r0 * 64 + col) = v0;
            *(float2*)(xs + r1 * 64 + col) = v1;
        }
    }
    __syncthreads();

    // ---- LN2 -> hb ----
    layernorm_bf16(xs, ln2_g, ln2_b, hb, tid);

    // ---- MLP output accumulator: mproj_b + residual ----
    float accO[4][4];
    #pragma unroll
    for (int j = 0; j < 4; ++j) {
        const int col = wn * 32 + j * 8 + t * 2;
        const float2 bb = *(const float2*)(mproj_b + col);
        const float2 x0 = *(const float2*)(xs + r0 * 64 + col);
        const float2 x1 = *(const float2*)(xs + r1 * 64 + col);
        accO[j][0] = bb.x + x0.x; accO[j][1] = bb.y + x0.y;
        accO[j][2] = bb.x + x1.x; accO[j][3] = bb.y + x1.y;
    }
    __syncthreads();

    // ---- MLP: 2 passes of 128 hidden cols ----
    __nv_bfloat16* fcact = qkvs;   // reuse, stride 136
    const uint32_t fcact_a = qkv_a;
    #pragma unroll
    for (int p = 0; p < 2; ++p) {
        copy_w(g_wfc + p * 128, 256, wb, 136, 64, 128, tid);
        __syncthreads();
        // fc + gelu -> fcact ; warp covers 64 cols in two 32-col subpasses
        #pragma unroll
        for (int q = 0; q < 2; ++q) {
            const int nb = wn * 64 + q * 32;
            float d[4][4];
            #pragma unroll
            for (int j = 0; j < 4; ++j) {
                const int col = p * 128 + nb + j * 8 + t * 2;
                d[j][0] = d[j][2] = __ldg(fc_b + col);
                d[j][1] = d[j][3] = __ldg(fc_b + col + 1);
            }
            mma_tile<4, 4>(hb_a, 72, wb_a, 136, wm * 16, nb, d, lane);
            #pragma unroll
            for (int j = 0; j < 4; ++j) {
                const int col = nb + j * 8 + t * 2;
                float v0 = 0.5f * d[j][0] * (1.0f + erff(d[j][0] * 0.70710678118654752f));
                float v1 = 0.5f * d[j][1] * (1.0f + erff(d[j][1] * 0.70710678118654752f));
                float v2 = 0.5f * d[j][2] * (1.0f + erff(d[j][2] * 0.70710678118654752f));
                float v3 = 0.5f * d[j][3] * (1.0f + erff(d[j][3] * 0.70710678118654752f));
                *(uint32_t*)(fcact + r0 * 136 + col) = packbf(v0, v1);
                *(uint32_t*)(fcact + r1 * 136 + col) = packbf(v2, v3);
            }
        }
        __syncthreads();
        copy_w(g_wmproj + p * 128 * 64, 64, wb, 72, 128, 64, tid);
        __syncthreads();
        mma_tile<8, 4>(fcact_a, 136, wb_a, 72, wm * 16, wn * 32, accO, lane);
        __syncthreads();
    }

    // ---- store output ----
    #pragma unroll
    for (int j = 0; j < 4; ++j) {
        const int col = wn * 32 + j * 8 + t * 2;
        *(float2*)(og + r0 * 64 + col) = make_float2(accO[j][0], accO[j][1]);
        *(float2*)(og + r1 * 64 + col) = make_float2(accO[j][2], accO[j][3]);
    }
}

extern "C" void kernel_launch(void* const* d_in, const int* in_sizes, int n_in,
                              void* d_out, int out_size) {
    const float* x       = (const float*)d_in[0];
    const float* ln1_g   = (const float*)d_in[1];
    const float* ln1_b   = (const float*)d_in[2];
    const float* qkv_w   = (const float*)d_in[3];
    const float* qkv_b   = (const float*)d_in[4];
    const float* aproj_w = (const float*)d_in[5];
    const float* aproj_b = (const float*)d_in[6];
    const float* ln2_g   = (const float*)d_in[7];
    const float* ln2_b   = (const float*)d_in[8];
    const float* fc_w    = (const float*)d_in[9];
    const float* fc_b    = (const float*)d_in[10];
    const float* mproj_w = (const float*)d_in[11];
    const float* mproj_b = (const float*)d_in[12];
    float* out = (float*)d_out;

    const int B = in_sizes[0] / (T_ * C_);

    convert_weights_kernel<<<64, 256>>>(qkv_w, aproj_w, fc_w, mproj_w);

    cudaFuncSetAttribute(block_tc_kernel,
                         cudaFuncAttributeMaxDynamicSharedMemorySize, SMEM_BYTES);
    block_tc_kernel<<<B, 256, SMEM_BYTES>>>(
        x, ln1_g, ln1_b, qkv_b, aproj_b, ln2_g, ln2_b, fc_b, mproj_b, out);
}

// round 4
// speedup vs baseline: 13.8634x; 1.0906x over previous
#include <cuda_runtime.h>
#include <cuda_bf16.h>
#include <math.h>
#include <stdint.h>

// Fused transformer block on tensor cores (bf16 mma.sync, fp32 accum).
// One CTA (256 thr = 8 warps) per batch element. B=4096, T=64, C=64, H=4, d=16.
// R4: weights pre-packed in mma B-fragment order in global (L2-resident);
// no weight smem staging, no B-side ldmatrix. smem 51.2KB.

#define T_ 64
#define C_ 64
#define EPS_ 1e-5f

// ---------------- fragment-packed bf16 weights (filled by prologue) ---------
// Layout: frag[(kt*NT + nt)*32 + lane] = {b0,b1} for mma.m16n8k16
//   b0 = pack(W[kt*16 + 2*tig][nt*8+gid], W[kt*16 + 2*tig + 1][nt*8+gid])
//   b1 = same with k+8, where gid = lane>>2, tig = lane&3.
__device__ uint2 g_fqkv[4 * 24 * 32];   // W 64x192
__device__ uint2 g_fap [4 * 8 * 32];    // W 64x64
__device__ uint2 g_ffc [4 * 32 * 32];   // W 64x256
__device__ uint2 g_fmp [16 * 8 * 32];   // W 256x64

__device__ __forceinline__ uint32_t packbf(float x, float y) {
    __nv_bfloat162 h = __floats2bfloat162_rn(x, y);
    return *(uint32_t*)&h;
}

__global__ void convert_weights_kernel(const float* __restrict__ qkv_w,
                                       const float* __restrict__ aproj_w,
                                       const float* __restrict__ fc_w,
                                       const float* __restrict__ mproj_w) {
    const int idx = blockIdx.x * blockDim.x + threadIdx.x;
    const int lane = idx & 31;
    const int rem = idx >> 5;
    const int gid = lane >> 2, tig = lane & 3;

    if (idx < 4 * 24 * 32) {            // qkv: KT=4, NT=24, ld=192
        const int kt = rem / 24, nt = rem % 24;
        const int k0 = kt * 16 + tig * 2, n = nt * 8 + gid;
        uint2 v;
        v.x = packbf(qkv_w[k0 * 192 + n], qkv_w[(k0 + 1) * 192 + n]);
        v.y = packbf(qkv_w[(k0 + 8) * 192 + n], qkv_w[(k0 + 9) * 192 + n]);
        g_fqkv[idx] = v;
    }
    if (idx < 4 * 8 * 32) {             // aproj: KT=4, NT=8, ld=64
        const int kt = rem / 8, nt = rem % 8;
        const int k0 = kt * 16 + tig * 2, n = nt * 8 + gid;
        uint2 v;
        v.x = packbf(aproj_w[k0 * 64 + n], aproj_w[(k0 + 1) * 64 + n]);
        v.y = packbf(aproj_w[(k0 + 8) * 64 + n], aproj_w[(k0 + 9) * 64 + n]);
        g_fap[idx] = v;
    }
    if (idx < 4 * 32 * 32) {            // fc: KT=4, NT=32, ld=256
        const int kt = rem / 32, nt = rem % 32;
        const int k0 = kt * 16 + tig * 2, n = nt * 8 + gid;
        uint2 v;
        v.x = packbf(fc_w[k0 * 256 + n], fc_w[(k0 + 1) * 256 + n]);
        v.y = packbf(fc_w[(k0 + 8) * 256 + n], fc_w[(k0 + 9) * 256 + n]);
        g_ffc[idx] = v;
    }
    if (idx < 16 * 8 * 32) {            // mproj: KT=16, NT=8, ld=64
        const int kt = rem / 8, nt = rem % 8;
        const int k0 = kt * 16 + tig * 2, n = nt * 8 + gid;
        uint2 v;
        v.x = packbf(mproj_w[k0 * 64 + n], mproj_w[(k0 + 1) * 64 + n]);
        v.y = packbf(mproj_w[(k0 + 8) * 64 + n], mproj_w[(k0 + 9) * 64 + n]);
        g_fmp[idx] = v;
    }
}

// ---------------- mma / ldmatrix helpers ------------------------------------
__device__ __forceinline__ uint32_t smem_u32(const void* p) {
    return (uint32_t)__cvta_generic_to_shared(p);
}
__device__ __forceinline__ void ldsm_x4(uint32_t a, uint32_t& r0, uint32_t& r1,
                                        uint32_t& r2, uint32_t& r3) {
    asm volatile("ldmatrix.sync.aligned.m8n8.x4.shared.b16 {%0,%1,%2,%3}, [%4];\n"
                 : "=r"(r0), "=r"(r1), "=r"(r2), "=r"(r3) : "r"(a));
}
__device__ __forceinline__ void ldsm_x2(uint32_t a, uint32_t& r0, uint32_t& r1) {
    asm volatile("ldmatrix.sync.aligned.m8n8.x2.shared.b16 {%0,%1}, [%2];\n"
                 : "=r"(r0), "=r"(r1) : "r"(a));
}
__device__ __forceinline__ void ldsm_x2t(uint32_t a, uint32_t& r0, uint32_t& r1) {
    asm volatile("ldmatrix.sync.aligned.m8n8.x2.trans.shared.b16 {%0,%1}, [%2];\n"
                 : "=r"(r0), "=r"(r1) : "r"(a));
}
__device__ __forceinline__ void mma16816(float& d0, float& d1, float& d2, float& d3,
                                         uint32_t a0, uint32_t a1, uint32_t a2,
                                         uint32_t a3, uint32_t b0, uint32_t b1) {
    asm volatile(
        "mma.sync.aligned.m16n8k16.row.col.f32.bf16.bf16.f32 "
        "{%0,%1,%2,%3},{%4,%5,%6,%7},{%8,%9},{%0,%1,%2,%3};\n"
        : "+f"(d0), "+f"(d1), "+f"(d2), "+f"(d3)
        : "r"(a0), "r"(a1), "r"(a2), "r"(a3), "r"(b0), "r"(b1));
}

// Load 4 k-tiles of A fragments (rows m0..m0+15, k 0..63) from smem.
__device__ __forceinline__ void lda_frags(uint32_t a_base, int lda, int m0,
                                          int lane, uint32_t a[4][4]) {
    const int ar = m0 + (lane & 15);
    const int ac = (lane >> 4) << 3;
    #pragma unroll
    for (int kt = 0; kt < 4; ++kt)
        ldsm_x4(a_base + (uint32_t)((ar * lda + kt * 16 + ac) * 2),
                a[kt][0], a[kt][1], a[kt][2], a[kt][3]);
}

// d[j] += A(4 k-tiles) @ Wfrag tiles nt0..nt0+3
__device__ __forceinline__ void mma_frag4(const uint32_t a[4][4],
                                          const uint2* __restrict__ frag,
                                          int NT, int nt0, int lane,
                                          float d[4][4]) {
    #pragma unroll
    for (int kt = 0; kt < 4; ++kt) {
        const uint2* fp = frag + (kt * NT + nt0) * 32 + lane;
        const uint2 b0 = __ldg(fp);
        const uint2 b1 = __ldg(fp + 32);
        const uint2 b2 = __ldg(fp + 64);
        const uint2 b3 = __ldg(fp + 96);
        mma16816(d[0][0], d[0][1], d[0][2], d[0][3],
                 a[kt][0], a[kt][1], a[kt][2], a[kt][3], b0.x, b0.y);
        mma16816(d[1][0], d[1][1], d[1][2], d[1][3],
                 a[kt][0], a[kt][1], a[kt][2], a[kt][3], b1.x, b1.y);
        mma16816(d[2][0], d[2][1], d[2][2], d[2][3],
                 a[kt][0], a[kt][1], a[kt][2], a[kt][3], b2.x, b2.y);
        mma16816(d[3][0], d[3][1], d[3][2], d[3][3],
                 a[kt][0], a[kt][1], a[kt][2], a[kt][3], b3.x, b3.y);
    }
}

// LayerNorm fp32 xs -> bf16 h (stride 72). 4 threads/row.
__device__ __forceinline__ void layernorm_bf16(const float* __restrict__ xs,
                                               const float* __restrict__ g,
                                               const float* __restrict__ b,
                                               __nv_bfloat16* __restrict__ h, int tid) {
    const int row = tid >> 2;
    const int c0 = (tid & 3) * 16;
    float v[16];
    float s = 0.f, s2 = 0.f;
    #pragma unroll
    for (int i = 0; i < 16; ++i) {
        v[i] = xs[row * 64 + c0 + i];
        s += v[i];
        s2 += v[i] * v[i];
    }
    s  += __shfl_xor_sync(0xffffffffu, s, 1);
    s2 += __shfl_xor_sync(0xffffffffu, s2, 1);
    s  += __shfl_xor_sync(0xffffffffu, s, 2);
    s2 += __shfl_xor_sync(0xffffffffu, s2, 2);
    const float mu = s * (1.0f / 64.0f);
    const float var = s2 * (1.0f / 64.0f) - mu * mu;
    const float rstd = rsqrtf(var + EPS_);
    #pragma unroll
    for (int i = 0; i < 8; ++i) {
        const float h0 = (v[2 * i] - mu) * rstd * g[c0 + 2 * i] + b[c0 + 2 * i];
        const float h1 = (v[2 * i + 1] - mu) * rstd * g[c0 + 2 * i + 1] + b[c0 + 2 * i + 1];
        *(uint32_t*)(h + row * 72 + c0 + 2 * i) = packbf(h0, h1);
    }
}

// smem: xs fp32 16384 | hb bf16 64x72 9216 | qkvs bf16 64x200 25600 = 51200 B
#define OFF_XS 0
#define OFF_HB 16384
#define OFF_QKV 25600
#define SMEM_BYTES 51200

__global__ __launch_bounds__(256, 3) void block_tc_kernel(
    const float* __restrict__ x,
    const float* __restrict__ ln1_g, const float* __restrict__ ln1_b,
    const float* __restrict__ qkv_b,
    const float* __restrict__ aproj_b,
    const float* __restrict__ ln2_g, const float* __restrict__ ln2_b,
    const float* __restrict__ fc_b,
    const float* __restrict__ mproj_b,
    float* __restrict__ out) {
    extern __shared__ char smem[];
    float* xs = (float*)(smem + OFF_XS);
    __nv_bfloat16* hb = (__nv_bfloat16*)(smem + OFF_HB);      // stride 72 (LN out / y)
    __nv_bfloat16* qkvs = (__nv_bfloat16*)(smem + OFF_QKV);   // stride 200 (qkv) / 136 (fcact)
    const uint32_t hb_a = smem_u32(hb);
    const uint32_t qkv_a = smem_u32(qkvs);

    const int tid = threadIdx.x;
    const int wid = tid >> 5;
    const int lane = tid & 31;
    const int g = lane >> 2;
    const int t = lane & 3;
    const int wm = wid & 3;       // m-tile 0..3
    const int wn = wid >> 2;      // n-half 0..1
    const int r0 = wm * 16 + g;
    const int r1 = r0 + 8;

    const size_t base = (size_t)blockIdx.x * (T_ * C_);
    const float* xg = x + base;
    float* og = out + base;

    // ---- load x ----
    {
        const float4* src = (const float4*)xg;
        float4* dst = (float4*)xs;
        #pragma unroll
        for (int i = tid; i < T_ * C_ / 4; i += 256) dst[i] = src[i];
    }
    __syncthreads();

    // ---- LN1 -> hb ----
    layernorm_bf16(xs, ln1_g, ln1_b, hb, tid);
    __syncthreads();

    // ---- QKV: A frags loaded once, 3 chunks of 64 cols ----
    {
        uint32_t a[4][4];
        lda_frags(hb_a, 72, wm * 16, lane, a);
        #pragma unroll
        for (int c = 0; c < 3; ++c) {
            float d[4][4];
            const int nt0 = c * 8 + wn * 4;
            #pragma unroll
            for (int j = 0; j < 4; ++j) {
                const float2 bb = *(const float2*)(qkv_b + (nt0 + j) * 8 + t * 2);
                d[j][0] = d[j][2] = bb.x;
                d[j][1] = d[j][3] = bb.y;
            }
            mma_frag4(a, g_fqkv, 24, nt0, lane, d);
            #pragma unroll
            for (int j = 0; j < 4; ++j) {
                const int col = (nt0 + j) * 8 + t * 2;
                *(uint32_t*)(qkvs + r0 * 200 + col) = packbf(d[j][0], d[j][1]);
                *(uint32_t*)(qkvs + r1 * 200 + col) = packbf(d[j][2], d[j][3]);
            }
        }
    }
    __syncthreads();

    // ---- attention (tensor cores, register softmax) ----
    {
        const int h = wid >> 1;
        const int half = wid & 1;
        #pragma unroll
        for (int mt = 0; mt < 2; ++mt) {
            const int rowbase = half * 32 + mt * 16;
            uint32_t qa0, qa1, qa2, qa3;
            {
                const int r = rowbase + (lane & 15);
                const int cq = h * 16 + ((lane >> 4) << 3);
                ldsm_x4(qkv_a + (uint32_t)((r * 200 + cq) * 2), qa0, qa1, qa2, qa3);
            }
            float s[8][4];
            #pragma unroll
            for (int j = 0; j < 8; ++j) {
                uint32_t b0, b1;
                const int kr = j * 8 + (lane & 7);
                const int kc = 64 + h * 16 + (lane & 8);
                ldsm_x2(qkv_a + (uint32_t)((kr * 200 + kc) * 2), b0, b1);
                s[j][0] = s[j][1] = s[j][2] = s[j][3] = 0.f;
                mma16816(s[j][0], s[j][1], s[j][2], s[j][3], qa0, qa1, qa2, qa3, b0, b1);
            }
            const int rA = rowbase + g, rB = rA + 8;
            float mA = -1e30f, mB = -1e30f;
            #pragma unroll
            for (int j = 0; j < 8; ++j) {
                #pragma unroll
                for (int e = 0; e < 2; ++e) {
                    const int col = j * 8 + t * 2 + e;
                    s[j][e]     = (col <= rA) ? s[j][e] * 0.25f     : -1e30f;
                    s[j][2 + e] = (col <= rB) ? s[j][2 + e] * 0.25f : -1e30f;
                    mA = fmaxf(mA, s[j][e]);
                    mB = fmaxf(mB, s[j][2 + e]);
                }
            }
            mA = fmaxf(mA, __shfl_xor_sync(0xffffffffu, mA, 1));
            mA = fmaxf(mA, __shfl_xor_sync(0xffffffffu, mA, 2));
            mB = fmaxf(mB, __shfl_xor_sync(0xffffffffu, mB, 1));
            mB = fmaxf(mB, __shfl_xor_sync(0xffffffffu, mB, 2));
            float sA = 0.f, sB = 0.f;
            #pragma unroll
            for (int j = 0; j < 8; ++j) {
                #pragma unroll
                for (int e = 0; e < 2; ++e) {
                    s[j][e] = __expf(s[j][e] - mA);
                    s[j][2 + e] = __expf(s[j][2 + e] - mB);
                    sA += s[j][e];
                    sB += s[j][2 + e];
                }
            }
            sA += __shfl_xor_sync(0xffffffffu, sA, 1);
            sA += __shfl_xor_sync(0xffffffffu, sA, 2);
            sB += __shfl_xor_sync(0xffffffffu, sB, 1);
            sB += __shfl_xor_sync(0xffffffffu, sB, 2);
            const float invA = 1.0f / sA, invB = 1.0f / sB;
            float y0[4] = {0.f, 0.f, 0.f, 0.f};
            float y1[4] = {0.f, 0.f, 0.f, 0.f};
            #pragma unroll
            for (int kk = 0; kk < 4; ++kk) {
                const uint32_t pa0 = packbf(s[2 * kk][0] * invA, s[2 * kk][1] * invA);
                const uint32_t pa1 = packbf(s[2 * kk][2] * invB, s[2 * kk][3] * invB);
                const uint32_t pa2 = packbf(s[2 * kk + 1][0] * invA, s[2 * kk + 1][1] * invA);
                const uint32_t pa3 = packbf(s[2 * kk + 1][2] * invB, s[2 * kk + 1][3] * invB);
                const int vr = kk * 16 + (lane & 15);
                uint32_t b0, b1;
                ldsm_x2t(qkv_a + (uint32_t)((vr * 200 + 128 + h * 16) * 2), b0, b1);
                mma16816(y0[0], y0[1], y0[2], y0[3], pa0, pa1, pa2, pa3, b0, b1);
                ldsm_x2t(qkv_a + (uint32_t)((vr * 200 + 128 + h * 16 + 8) * 2), b0, b1);
                mma16816(y1[0], y1[1], y1[2], y1[3], pa0, pa1, pa2, pa3, b0, b1);
            }
            const int cy = h * 16 + t * 2;
            *(uint32_t*)(hb + (rowbase + g) * 72 + cy)         = packbf(y0[0], y0[1]);
            *(uint32_t*)(hb + (rowbase + g + 8) * 72 + cy)     = packbf(y0[2], y0[3]);
            *(uint32_t*)(hb + (rowbase + g) * 72 + cy + 8)     = packbf(y1[0], y1[1]);
            *(uint32_t*)(hb + (rowbase + g + 8) * 72 + cy + 8) = packbf(y1[2], y1[3]);
        }
    }
    __syncthreads();

    // ---- attention proj + residual into xs ----
    {
        uint32_t a[4][4];
        lda_frags(hb_a, 72, wm * 16, lane, a);
        float d[4][4];
        const int nt0 = wn * 4;
        #pragma unroll
        for (int j = 0; j < 4; ++j) {
            const float2 bb = *(const float2*)(aproj_b + (nt0 + j) * 8 + t * 2);
            d[j][0] = d[j][2] = bb.x;
            d[j][1] = d[j][3] = bb.y;
        }
        mma_frag4(a, g_fap, 8, nt0, lane, d);
        #pragma unroll
        for (int j = 0; j < 4; ++j) {
            const int col = (nt0 + j) * 8 + t * 2;
            float2 v0 = *(float2*)(xs + r0 * 64 + col);
            float2 v1 = *(float2*)(xs + r1 * 64 + col);
            v0.x += d[j][0]; v0.y += d[j][1];
            v1.x += d[j][2]; v1.y += d[j][3];
            *(float2*)(xs + r0 * 64 + col) = v0;
            *(float2*)(xs + r1 * 64 + col) = v1;
        }
    }
    __syncthreads();

    // ---- LN2 -> hb ----
    layernorm_bf16(xs, ln2_g, ln2_b, hb, tid);

    // ---- MLP output accumulator: mproj_b + residual ----
    float accO[4][4];
    #pragma unroll
    for (int j = 0; j < 4; ++j) {
        const int col = wn * 32 + j * 8 + t * 2;
        const float2 bb = *(const float2*)(mproj_b + col);
        const float2 x0 = *(const float2*)(xs + r0 * 64 + col);
        const float2 x1 = *(const float2*)(xs + r1 * 64 + col);
        accO[j][0] = bb.x + x0.x; accO[j][1] = bb.y + x0.y;
        accO[j][2] = bb.x + x1.x; accO[j][3] = bb.y + x1.y;
    }
    __syncthreads();

    // ---- MLP: 2 passes of 128 hidden cols ----
    __nv_bfloat16* fcact = qkvs;   // reuse, stride 136
    {
        uint32_t a[4][4];                       // LN2 A frags, reused all passes
        lda_frags(hb_a, 72, wm * 16, lane, a);
        #pragma unroll
        for (int p = 0; p < 2; ++p) {
            // fc + gelu -> fcact (warp covers 64 of 128 cols, 2 subpasses)
            #pragma unroll
            for (int q = 0; q < 2; ++q) {
                const int nt0 = p * 16 + wn * 8 + q * 4;   // global fc tile idx
                float d[4][4];
                #pragma unroll
                for (int j = 0; j < 4; ++j) {
                    const float2 bb = *(const float2*)(fc_b + (nt0 + j) * 8 + t * 2);
                    d[j][0] = d[j][2] = bb.x;
                    d[j][1] = d[j][3] = bb.y;
                }
                mma_frag4(a, g_ffc, 32, nt0, lane, d);
                #pragma unroll
                for (int j = 0; j < 4; ++j) {
                    const int col = wn * 64 + q * 32 + j * 8 + t * 2;  // local 0..127
                    float v0 = 0.5f * d[j][0] * (1.0f + erff(d[j][0] * 0.70710678118654752f));
                    float v1 = 0.5f * d[j][1] * (1.0f + erff(d[j][1] * 0.70710678118654752f));
                    float v2 = 0.5f * d[j][2] * (1.0f + erff(d[j][2] * 0.70710678118654752f));
                    float v3 = 0.5f * d[j][3] * (1.0f + erff(d[j][3] * 0.70710678118654752f));
                    *(uint32_t*)(fcact + r0 * 136 + col) = packbf(v0, v1);
                    *(uint32_t*)(fcact + r1 * 136 + col) = packbf(v2, v3);
                }
            }
            __syncthreads();
            // accO += fcact[64x128] @ mproj[p*128.., :]
            {
                const int ar = wm * 16 + (lane & 15);
                const int ac = (lane >> 4) << 3;
                #pragma unroll
                for (int kt = 0; kt < 8; ++kt) {
                    uint32_t a0, a1, a2, a3;
                    ldsm_x4(qkv_a + (uint32_t)((ar * 136 + kt * 16 + ac) * 2),
                            a0, a1, a2, a3);
                    const uint2* fp = g_fmp + ((p * 8 + kt) * 8 + wn * 4) * 32 + lane;
                    const uint2 b0 = __ldg(fp);
                    const uint2 b1 = __ldg(fp + 32);
                    const uint2 b2 = __ldg(fp + 64);
                    const uint2 b3 = __ldg(fp + 96);
                    mma16816(accO[0][0], accO[0][1], accO[0][2], accO[0][3],
                             a0, a1, a2, a3, b0.x, b0.y);
                    mma16816(accO[1][0], accO[1][1], accO[1][2], accO[1][3],
                             a0, a1, a2, a3, b1.x, b1.y);
                    mma16816(accO[2][0], accO[2][1], accO[2][2], accO[2][3],
                             a0, a1, a2, a3, b2.x, b2.y);
                    mma16816(accO[3][0], accO[3][1], accO[3][2], accO[3][3],
                             a0, a1, a2, a3, b3.x, b3.y);
                }
            }
            __syncthreads();
        }
    }

    // ---- store output ----
    #pragma unroll
    for (int j = 0; j < 4; ++j) {
        const int col = wn * 32 + j * 8 + t * 2;
        *(float2*)(og + r0 * 64 + col) = make_float2(accO[j][0], accO[j][1]);
        *(float2*)(og + r1 * 64 + col) = make_float2(accO[j][2], accO[j][3]);
    }
}

extern "C" void kernel_launch(void* const* d_in, const int* in_sizes, int n_in,
                              void* d_out, int out_size) {
    const float* x       = (const float*)d_in[0];
    const float* ln1_g   = (const float*)d_in[1];
    const float* ln1_b   = (const float*)d_in[2];
    const float* qkv_w   = (const float*)d_in[3];
    const float* qkv_b   = (const float*)d_in[4];
    const float* aproj_w = (const float*)d_in[5];
    const float* aproj_b = (const float*)d_in[6];
    const float* ln2_g   = (const float*)d_in[7];
    const float* ln2_b   = (const float*)d_in[8];
    const float* fc_w    = (const float*)d_in[9];
    const float* fc_b    = (const float*)d_in[10];
    const float* mproj_w = (const float*)d_in[11];
    const float* mproj_b = (const float*)d_in[12];
    float* out = (float*)d_out;

    const int B = in_sizes[0] / (T_ * C_);

    convert_weights_kernel<<<16, 256>>>(qkv_w, aproj_w, fc_w, mproj_w);

    cudaFuncSetAttribute(block_tc_kernel,
                         cudaFuncAttributeMaxDynamicSharedMemorySize, SMEM_BYTES);
    block_tc_kernel<<<B, 256, SMEM_BYTES>>>(
        x, ln1_g, ln1_b, qkv_b, aproj_b, ln2_g, ln2_b, fc_b, mproj_b, out);
}

// round 5
// speedup vs baseline: 17.3438x; 1.2511x over previous
#include <cuda_runtime.h>
#include <cuda_bf16.h>
#include <math.h>
#include <stdint.h>

// Fused transformer block on tensor cores (bf16 mma.sync, fp32 accum).
// One CTA (256 thr = 8 warps) per batch element. B=4096, T=64, C=64, H=4, d=16.
// R5: warp owns an N-slice and loops over all 4 M-tiles -> each weight
// B-fragment LDG serves 4 mma (weight LDG cut 4x). tanh-approx GELU.
// Vectorized LN. Single-pass MLP (fcact 64x264 bf16). smem 59.4KB, 3 CTAs/SM.

#define T_ 64
#define C_ 64
#define EPS_ 1e-5f

// ---------------- fragment-packed bf16 weights (filled by prologue) ---------
// frag[(kt*NT + nt)*32 + lane] = {b0,b1} for mma.m16n8k16 B operand.
__device__ uint2 g_fqkv[4 * 24 * 32];   // W 64x192
__device__ uint2 g_fap [4 * 8 * 32];    // W 64x64
__device__ uint2 g_ffc [4 * 32 * 32];   // W 64x256
__device__ uint2 g_fmp [16 * 8 * 32];   // W 256x64

__device__ __forceinline__ uint32_t packbf(float x, float y) {
    __nv_bfloat162 h = __floats2bfloat162_rn(x, y);
    return *(uint32_t*)&h;
}

__global__ void convert_weights_kernel(const float* __restrict__ qkv_w,
                                       const float* __restrict__ aproj_w,
                                       const float* __restrict__ fc_w,
                                       const float* __restrict__ mproj_w) {
    const int idx = blockIdx.x * blockDim.x + threadIdx.x;
    const int lane = idx & 31;
    const int rem = idx >> 5;
    const int gid = lane >> 2, tig = lane & 3;

    if (idx < 4 * 24 * 32) {
        const int kt = rem / 24, nt = rem % 24;
        const int k0 = kt * 16 + tig * 2, n = nt * 8 + gid;
        uint2 v;
        v.x = packbf(qkv_w[k0 * 192 + n], qkv_w[(k0 + 1) * 192 + n]);
        v.y = packbf(qkv_w[(k0 + 8) * 192 + n], qkv_w[(k0 + 9) * 192 + n]);
        g_fqkv[idx] = v;
    }
    if (idx < 4 * 8 * 32) {
        const int kt = rem / 8, nt = rem % 8;
        const int k0 = kt * 16 + tig * 2, n = nt * 8 + gid;
        uint2 v;
        v.x = packbf(aproj_w[k0 * 64 + n], aproj_w[(k0 + 1) * 64 + n]);
        v.y = packbf(aproj_w[(k0 + 8) * 64 + n], aproj_w[(k0 + 9) * 64 + n]);
        g_fap[idx] = v;
    }
    if (idx < 4 * 32 * 32) {
        const int kt = rem / 32, nt = rem % 32;
        const int k0 = kt * 16 + tig * 2, n = nt * 8 + gid;
        uint2 v;
        v.x = packbf(fc_w[k0 * 256 + n], fc_w[(k0 + 1) * 256 + n]);
        v.y = packbf(fc_w[(k0 + 8) * 256 + n], fc_w[(k0 + 9) * 256 + n]);
        g_ffc[idx] = v;
    }
    if (idx < 16 * 8 * 32) {
        const int kt = rem / 8, nt = rem % 8;
        const int k0 = kt * 16 + tig * 2, n = nt * 8 + gid;
        uint2 v;
        v.x = packbf(mproj_w[k0 * 64 + n], mproj_w[(k0 + 1) * 64 + n]);
        v.y = packbf(mproj_w[(k0 + 8) * 64 + n], mproj_w[(k0 + 9) * 64 + n]);
        g_fmp[idx] = v;
    }
}

// ---------------- helpers ----------------------------------------------------
__device__ __forceinline__ uint32_t smem_u32(const void* p) {
    return (uint32_t)__cvta_generic_to_shared(p);
}
__device__ __forceinline__ void ldsm_x4(uint32_t a, uint32_t& r0, uint32_t& r1,
                                        uint32_t& r2, uint32_t& r3) {
    asm volatile("ldmatrix.sync.aligned.m8n8.x4.shared.b16 {%0,%1,%2,%3}, [%4];\n"
                 : "=r"(r0), "=r"(r1), "=r"(r2), "=r"(r3) : "r"(a));
}
__device__ __forceinline__ void ldsm_x2(uint32_t a, uint32_t& r0, uint32_t& r1) {
    asm volatile("ldmatrix.sync.aligned.m8n8.x2.shared.b16 {%0,%1}, [%2];\n"
                 : "=r"(r0), "=r"(r1) : "r"(a));
}
__device__ __forceinline__ void ldsm_x2t(uint32_t a, uint32_t& r0, uint32_t& r1) {
    asm volatile("ldmatrix.sync.aligned.m8n8.x2.trans.shared.b16 {%0,%1}, [%2];\n"
                 : "=r"(r0), "=r"(r1) : "r"(a));
}
__device__ __forceinline__ void mma16816(float& d0, float& d1, float& d2, float& d3,
                                         uint32_t a0, uint32_t a1, uint32_t a2,
                                         uint32_t a3, uint32_t b0, uint32_t b1) {
    asm volatile(
        "mma.sync.aligned.m16n8k16.row.col.f32.bf16.bf16.f32 "
        "{%0,%1,%2,%3},{%4,%5,%6,%7},{%8,%9},{%0,%1,%2,%3};\n"
        : "+f"(d0), "+f"(d1), "+f"(d2), "+f"(d3)
        : "r"(a0), "r"(a1), "r"(a2), "r"(a3), "r"(b0), "r"(b1));
}
__device__ __forceinline__ float gelu_fast(float v) {
    float u = v * (0.7978845608f + 0.0356774081f * v * v);
    float th;
    asm("tanh.approx.f32 %0, %1;\n" : "=f"(th) : "f"(u));
    return 0.5f * v * (1.0f + th);
}

// LayerNorm fp32 xs -> bf16 h (stride 72). 4 threads/row, vectorized loads.
__device__ __forceinline__ void layernorm_bf16(const float* __restrict__ xs,
                                               const float* __restrict__ g,
                                               const float* __restrict__ b,
                                               __nv_bfloat16* __restrict__ h, int tid) {
    const int row = tid >> 2;
    const int c0 = (tid & 3) * 16;
    const float4* src = (const float4*)(xs + row * 64 + c0);
    float4 v4[4];
    float s = 0.f, s2 = 0.f;
    #pragma unroll
    for (int i = 0; i < 4; ++i) {
        v4[i] = src[i];
        s += v4[i].x + v4[i].y + v4[i].z + v4[i].w;
        s2 += v4[i].x * v4[i].x + v4[i].y * v4[i].y
            + v4[i].z * v4[i].z + v4[i].w * v4[i].w;
    }
    s  += __shfl_xor_sync(0xffffffffu, s, 1);
    s2 += __shfl_xor_sync(0xffffffffu, s2, 1);
    s  += __shfl_xor_sync(0xffffffffu, s, 2);
    s2 += __shfl_xor_sync(0xffffffffu, s2, 2);
    const float mu = s * (1.0f / 64.0f);
    const float var = s2 * (1.0f / 64.0f) - mu * mu;
    const float rstd = rsqrtf(var + EPS_);
    const float* v = (const float*)v4;
    #pragma unroll
    for (int i = 0; i < 8; ++i) {
        const float h0 = (v[2 * i] - mu) * rstd * g[c0 + 2 * i] + b[c0 + 2 * i];
        const float h1 = (v[2 * i + 1] - mu) * rstd * g[c0 + 2 * i + 1] + b[c0 + 2 * i + 1];
        *(uint32_t*)(h + row * 72 + c0 + 2 * i) = packbf(h0, h1);
    }
}

// smem: xs fp32 16384 | hb bf16 64x72 9216 | act bf16 (qkv 64x200 / fc 64x264)
#define OFF_XS 0
#define OFF_HB 16384
#define OFF_ACT 25600
#define SMEM_BYTES (25600 + 64 * 264 * 2)   // 59392

__global__ __launch_bounds__(256, 3) void block_tc_kernel(
    const float* __restrict__ x,
    const float* __restrict__ ln1_g, const float* __restrict__ ln1_b,
    const float* __restrict__ qkv_b,
    const float* __restrict__ aproj_b,
    const float* __restrict__ ln2_g, const float* __restrict__ ln2_b,
    const float* __restrict__ fc_b,
    const float* __restrict__ mproj_b,
    float* __restrict__ out) {
    extern __shared__ char smem[];
    float* xs = (float*)(smem + OFF_XS);
    __nv_bfloat16* hb = (__nv_bfloat16*)(smem + OFF_HB);      // stride 72
    __nv_bfloat16* qkvs = (__nv_bfloat16*)(smem + OFF_ACT);   // stride 200 / 264
    const uint32_t hb_a = smem_u32(hb);
    const uint32_t act_a = smem_u32(qkvs);

    const int tid = threadIdx.x;
    const int wid = tid >> 5;
    const int lane = tid & 31;
    const int g = lane >> 2;
    const int t = lane & 3;
    const int lr = lane & 15;             // ldsm row-in-tile
    const int lc = (lane >> 4) << 3;      // ldsm col offset

    const size_t base = (size_t)blockIdx.x * (T_ * C_);
    const float* xg = x + base;
    float* og = out + base;

    // ---- load x ----
    {
        const float4* src = (const float4*)xg;
        float4* dst = (float4*)xs;
        #pragma unroll
        for (int i = tid; i < T_ * C_ / 4; i += 256) dst[i] = src[i];
    }
    __syncthreads();

    // ---- LN1 -> hb ----
    layernorm_bf16(xs, ln1_g, ln1_b, hb, tid);
    __syncthreads();

    // ---- QKV: warp owns cols [24w, 24w+24), loops all 4 m-tiles ----
    {
        uint2 B[4][3];
        #pragma unroll
        for (int kt = 0; kt < 4; ++kt)
            #pragma unroll
            for (int j = 0; j < 3; ++j)
                B[kt][j] = __ldg(g_fqkv + ((kt * 24 + wid * 3 + j) << 5) + lane);
        float2 bias[3];
        #pragma unroll
        for (int j = 0; j < 3; ++j)
            bias[j] = *(const float2*)(qkv_b + (wid * 3 + j) * 8 + t * 2);
        #pragma unroll
        for (int mt = 0; mt < 4; ++mt) {
            float d[3][4];
            #pragma unroll
            for (int j = 0; j < 3; ++j) {
                d[j][0] = d[j][2] = bias[j].x;
                d[j][1] = d[j][3] = bias[j].y;
            }
            #pragma unroll
            for (int kt = 0; kt < 4; ++kt) {
                uint32_t a0, a1, a2, a3;
                ldsm_x4(hb_a + (uint32_t)(((mt * 16 + lr) * 72 + kt * 16 + lc) * 2),
                        a0, a1, a2, a3);
                #pragma unroll
                for (int j = 0; j < 3; ++j)
                    mma16816(d[j][0], d[j][1], d[j][2], d[j][3],
                             a0, a1, a2, a3, B[kt][j].x, B[kt][j].y);
            }
            const int rr0 = mt * 16 + g, rr1 = rr0 + 8;
            #pragma unroll
            for (int j = 0; j < 3; ++j) {
                const int col = (wid * 3 + j) * 8 + t * 2;
                *(uint32_t*)(qkvs + rr0 * 200 + col) = packbf(d[j][0], d[j][1]);
                *(uint32_t*)(qkvs + rr1 * 200 + col) = packbf(d[j][2], d[j][3]);
            }
        }
    }
    __syncthreads();

    // ---- attention (tensor cores, register softmax) ----
    {
        const int h = wid >> 1;
        const int half = wid & 1;
        #pragma unroll
        for (int mt = 0; mt < 2; ++mt) {
            const int rowbase = half * 32 + mt * 16;
            uint32_t qa0, qa1, qa2, qa3;
            ldsm_x4(act_a + (uint32_t)(((rowbase + lr) * 200 + h * 16 + lc) * 2),
                    qa0, qa1, qa2, qa3);
            float s[8][4];
            #pragma unroll
            for (int j = 0; j < 8; ++j) {
                uint32_t b0, b1;
                const int kr = j * 8 + (lane & 7);
                const int kc = 64 + h * 16 + (lane & 8);
                ldsm_x2(act_a + (uint32_t)((kr * 200 + kc) * 2), b0, b1);
                s[j][0] = s[j][1] = s[j][2] = s[j][3] = 0.f;
                mma16816(s[j][0], s[j][1], s[j][2], s[j][3], qa0, qa1, qa2, qa3, b0, b1);
            }
            const int rA = rowbase + g, rB = rA + 8;
            float mA = -1e30f, mB = -1e30f;
            #pragma unroll
            for (int j = 0; j < 8; ++j) {
                #pragma unroll
                for (int e = 0; e < 2; ++e) {
                    const int col = j * 8 + t * 2 + e;
                    s[j][e]     = (col <= rA) ? s[j][e] * 0.25f     : -1e30f;
                    s[j][2 + e] = (col <= rB) ? s[j][2 + e] * 0.25f : -1e30f;
                    mA = fmaxf(mA, s[j][e]);
                    mB = fmaxf(mB, s[j][2 + e]);
                }
            }
            mA = fmaxf(mA, __shfl_xor_sync(0xffffffffu, mA, 1));
            mA = fmaxf(mA, __shfl_xor_sync(0xffffffffu, mA, 2));
            mB = fmaxf(mB, __shfl_xor_sync(0xffffffffu, mB, 1));
            mB = fmaxf(mB, __shfl_xor_sync(0xffffffffu, mB, 2));
            float sA = 0.f, sB = 0.f;
            #pragma unroll
            for (int j = 0; j < 8; ++j) {
                #pragma unroll
                for (int e = 0; e < 2; ++e) {
                    s[j][e] = __expf(s[j][e] - mA);
                    s[j][2 + e] = __expf(s[j][2 + e] - mB);
                    sA += s[j][e];
                    sB += s[j][2 + e];
                }
            }
            sA += __shfl_xor_sync(0xffffffffu, sA, 1);
            sA += __shfl_xor_sync(0xffffffffu, sA, 2);
            sB += __shfl_xor_sync(0xffffffffu, sB, 1);
            sB += __shfl_xor_sync(0xffffffffu, sB, 2);
            const float invA = 1.0f / sA, invB = 1.0f / sB;
            float y0[4] = {0.f, 0.f, 0.f, 0.f};
            float y1[4] = {0.f, 0.f, 0.f, 0.f};
            #pragma unroll
            for (int kk = 0; kk < 4; ++kk) {
                const uint32_t pa0 = packbf(s[2 * kk][0] * invA, s[2 * kk][1] * invA);
                const uint32_t pa1 = packbf(s[2 * kk][2] * invB, s[2 * kk][3] * invB);
                const uint32_t pa2 = packbf(s[2 * kk + 1][0] * invA, s[2 * kk + 1][1] * invA);
                const uint32_t pa3 = packbf(s[2 * kk + 1][2] * invB, s[2 * kk + 1][3] * invB);
                const int vr = kk * 16 + lr;
                uint32_t b0, b1;
                ldsm_x2t(act_a + (uint32_t)((vr * 200 + 128 + h * 16) * 2), b0, b1);
                mma16816(y0[0], y0[1], y0[2], y0[3], pa0, pa1, pa2, pa3, b0, b1);
                ldsm_x2t(act_a + (uint32_t)((vr * 200 + 128 + h * 16 + 8) * 2), b0, b1);
                mma16816(y1[0], y1[1], y1[2], y1[3], pa0, pa1, pa2, pa3, b0, b1);
            }
            const int cy = h * 16 + t * 2;
            *(uint32_t*)(hb + (rowbase + g) * 72 + cy)         = packbf(y0[0], y0[1]);
            *(uint32_t*)(hb + (rowbase + g + 8) * 72 + cy)     = packbf(y0[2], y0[3]);
            *(uint32_t*)(hb + (rowbase + g) * 72 + cy + 8)     = packbf(y1[0], y1[1]);
            *(uint32_t*)(hb + (rowbase + g + 8) * 72 + cy + 8) = packbf(y1[2], y1[3]);
        }
    }
    __syncthreads();

    // ---- attention proj + residual into xs (warp owns cols [8w, 8w+8)) ----
    {
        uint2 B[4];
        #pragma unroll
        for (int kt = 0; kt < 4; ++kt)
            B[kt] = __ldg(g_fap + ((kt * 8 + wid) << 5) + lane);
        const float2 bias = *(const float2*)(aproj_b + wid * 8 + t * 2);
        const int col = wid * 8 + t * 2;
        #pragma unroll
        for (int mt = 0; mt < 4; ++mt) {
            float d[4];
            d[0] = d[2] = bias.x;
            d[1] = d[3] = bias.y;
            #pragma unroll
            for (int kt = 0; kt < 4; ++kt) {
                uint32_t a0, a1, a2, a3;
                ldsm_x4(hb_a + (uint32_t)(((mt * 16 + lr) * 72 + kt * 16 + lc) * 2),
                        a0, a1, a2, a3);
                mma16816(d[0], d[1], d[2], d[3], a0, a1, a2, a3, B[kt].x, B[kt].y);
            }
            const int rr0 = mt * 16 + g, rr1 = rr0 + 8;
            float2 v0 = *(float2*)(xs + rr0 * 64 + col);
            float2 v1 = *(float2*)(xs + rr1 * 64 + col);
            v0.x += d[0]; v0.y += d[1];
            v1.x += d[2]; v1.y += d[3];
            *(float2*)(xs + rr0 * 64 + col) = v0;
            *(float2*)(xs + rr1 * 64 + col) = v1;
        }
    }
    __syncthreads();

    // ---- LN2 -> hb ----
    layernorm_bf16(xs, ln2_g, ln2_b, hb, tid);

    // ---- MLP output accumulator init: mproj_b + residual ----
    float accO[4][4];   // [mt][frag]
    {
        const int col = wid * 8 + t * 2;
        const float2 bb = *(const float2*)(mproj_b + col);
        #pragma unroll
        for (int mt = 0; mt < 4; ++mt) {
            const float2 x0 = *(const float2*)(xs + (mt * 16 + g) * 64 + col);
            const float2 x1 = *(const float2*)(xs + (mt * 16 + g + 8) * 64 + col);
            accO[mt][0] = bb.x + x0.x; accO[mt][1] = bb.y + x0.y;
            accO[mt][2] = bb.x + x1.x; accO[mt][3] = bb.y + x1.y;
        }
    }
    __syncthreads();

    // ---- FC + GELU: warp owns cols [32w, 32w+32) of 256 -> fcact (stride 264)
    __nv_bfloat16* fcact = qkvs;
    {
        uint2 B[4][4];
        #pragma unroll
        for (int kt = 0; kt < 4; ++kt)
            #pragma unroll
            for (int j = 0; j < 4; ++j)
                B[kt][j] = __ldg(g_ffc + ((kt * 32 + wid * 4 + j) << 5) + lane);
        float2 bias[4];
        #pragma unroll
        for (int j = 0; j < 4; ++j)
            bias[j] = *(const float2*)(fc_b + (wid * 4 + j) * 8 + t * 2);
        #pragma unroll
        for (int mt = 0; mt < 4; ++mt) {
            float d[4][4];
            #pragma unroll
            for (int j = 0; j < 4; ++j) {
                d[j][0] = d[j][2] = bias[j].x;
                d[j][1] = d[j][3] = bias[j].y;
            }
            #pragma unroll
            for (int kt = 0; kt < 4; ++kt) {
                uint32_t a0, a1, a2, a3;
                ldsm_x4(hb_a + (uint32_t)(((mt * 16 + lr) * 72 + kt * 16 + lc) * 2),
                        a0, a1, a2, a3);
                #pragma unroll
                for (int j = 0; j < 4; ++j)
                    mma16816(d[j][0], d[j][1], d[j][2], d[j][3],
                             a0, a1, a2, a3, B[kt][j].x, B[kt][j].y);
            }
            const int rr0 = mt * 16 + g, rr1 = rr0 + 8;
            #pragma unroll
            for (int j = 0; j < 4; ++j) {
                const int col = (wid * 4 + j) * 8 + t * 2;
                *(uint32_t*)(fcact + rr0 * 264 + col) =
                    packbf(gelu_fast(d[j][0]), gelu_fast(d[j][1]));
                *(uint32_t*)(fcact + rr1 * 264 + col) =
                    packbf(gelu_fast(d[j][2]), gelu_fast(d[j][3]));
            }
        }
    }
    __syncthreads();

    // ---- MLP proj: K=256, warp owns cols [8w, 8w+8) ----
    {
        uint2 B[16];
        #pragma unroll
        for (int kt = 0; kt < 16; ++kt)
            B[kt] = __ldg(g_fmp + ((kt * 8 + wid) << 5) + lane);
        #pragma unroll
        for (int mt = 0; mt < 4; ++mt) {
            #pragma unroll
            for (int kt = 0; kt < 16; ++kt) {
                uint32_t a0, a1, a2, a3;
                ldsm_x4(act_a + (uint32_t)(((mt * 16 + lr) * 264 + kt * 16 + lc) * 2),
                        a0, a1, a2, a3);
                mma16816(accO[mt][0], accO[mt][1], accO[mt][2], accO[mt][3],
                         a0, a1, a2, a3, B[kt].x, B[kt].y);
            }
        }
    }

    // ---- store output ----
    {
        const int col = wid * 8 + t * 2;
        #pragma unroll
        for (int mt = 0; mt < 4; ++mt) {
            const int rr0 = mt * 16 + g, rr1 = rr0 + 8;
            *(float2*)(og + rr0 * 64 + col) = make_float2(accO[mt][0], accO[mt][1]);
            *(float2*)(og + rr1 * 64 + col) = make_float2(accO[mt][2], accO[mt][3]);
        }
    }
}

extern "C" void kernel_launch(void* const* d_in, const int* in_sizes, int n_in,
                              void* d_out, int out_size) {
    const float* x       = (const float*)d_in[0];
    const float* ln1_g   = (const float*)d_in[1];
    const float* ln1_b   = (const float*)d_in[2];
    const float* qkv_w   = (const float*)d_in[3];
    const float* qkv_b   = (const float*)d_in[4];
    const float* aproj_w = (const float*)d_in[5];
    const float* aproj_b = (const float*)d_in[6];
    const float* ln2_g   = (const float*)d_in[7];
    const float* ln2_b   = (const float*)d_in[8];
    const float* fc_w    = (const float*)d_in[9];
    const float* fc_b    = (const float*)d_in[10];
    const float* mproj_w = (const float*)d_in[11];
    const float* mproj_b = (const float*)d_in[12];
    float* out = (float*)d_out;

    const int B = in_sizes[0] / (T_ * C_);

    convert_weights_kernel<<<16, 256>>>(qkv_w, aproj_w, fc_w, mproj_w);

    cudaFuncSetAttribute(block_tc_kernel,
                         cudaFuncAttributeMaxDynamicSharedMemorySize, SMEM_BYTES);
    block_tc_kernel<<<B, 256, SMEM_BYTES>>>(
        x, ln1_g, ln1_b, qkv_b, aproj_b, ln2_g, ln2_b, fc_b, mproj_b, out);
}

// round 6
// speedup vs baseline: 18.6967x; 1.0780x over previous
#include <cuda_runtime.h>
#include <cuda_bf16.h>
#include <math.h>
#include <stdint.h>

// Fused transformer block on tensor cores (bf16 mma.sync, fp32 accum).
// One CTA (256 thr = 8 warps) per batch element. B=4096, T=64, C=64, H=4, d=16.
// R6: mproj/aproj use 2m x 2n warp tiles so each ldsm/LDG feeds multiple mma;
// attention K/V loads use ldmatrix.x4 (half the instructions).

#define T_ 64
#define C_ 64
#define EPS_ 1e-5f

// ---------------- fragment-packed bf16 weights (filled by prologue) ---------
__device__ uint2 g_fqkv[4 * 24 * 32];   // W 64x192
__device__ uint2 g_fap [4 * 8 * 32];    // W 64x64
__device__ uint2 g_ffc [4 * 32 * 32];   // W 64x256
__device__ uint2 g_fmp [16 * 8 * 32];   // W 256x64

__device__ __forceinline__ uint32_t packbf(float x, float y) {
    __nv_bfloat162 h = __floats2bfloat162_rn(x, y);
    return *(uint32_t*)&h;
}

__global__ void convert_weights_kernel(const float* __restrict__ qkv_w,
                                       const float* __restrict__ aproj_w,
                                       const float* __restrict__ fc_w,
                                       const float* __restrict__ mproj_w) {
    const int idx = blockIdx.x * blockDim.x + threadIdx.x;
    const int lane = idx & 31;
    const int rem = idx >> 5;
    const int gid = lane >> 2, tig = lane & 3;

    if (idx < 4 * 24 * 32) {
        const int kt = rem / 24, nt = rem % 24;
        const int k0 = kt * 16 + tig * 2, n = nt * 8 + gid;
        uint2 v;
        v.x = packbf(qkv_w[k0 * 192 + n], qkv_w[(k0 + 1) * 192 + n]);
        v.y = packbf(qkv_w[(k0 + 8) * 192 + n], qkv_w[(k0 + 9) * 192 + n]);
        g_fqkv[idx] = v;
    }
    if (idx < 4 * 8 * 32) {
        const int kt = rem / 8, nt = rem % 8;
        const int k0 = kt * 16 + tig * 2, n = nt * 8 + gid;
        uint2 v;
        v.x = packbf(aproj_w[k0 * 64 + n], aproj_w[(k0 + 1) * 64 + n]);
        v.y = packbf(aproj_w[(k0 + 8) * 64 + n], aproj_w[(k0 + 9) * 64 + n]);
        g_fap[idx] = v;
    }
    if (idx < 4 * 32 * 32) {
        const int kt = rem / 32, nt = rem % 32;
        const int k0 = kt * 16 + tig * 2, n = nt * 8 + gid;
        uint2 v;
        v.x = packbf(fc_w[k0 * 256 + n], fc_w[(k0 + 1) * 256 + n]);
        v.y = packbf(fc_w[(k0 + 8) * 256 + n], fc_w[(k0 + 9) * 256 + n]);
        g_ffc[idx] = v;
    }
    if (idx < 16 * 8 * 32) {
        const int kt = rem / 8, nt = rem % 8;
        const int k0 = kt * 16 + tig * 2, n = nt * 8 + gid;
        uint2 v;
        v.x = packbf(mproj_w[k0 * 64 + n], mproj_w[(k0 + 1) * 64 + n]);
        v.y = packbf(mproj_w[(k0 + 8) * 64 + n], mproj_w[(k0 + 9) * 64 + n]);
        g_fmp[idx] = v;
    }
}

// ---------------- helpers ----------------------------------------------------
__device__ __forceinline__ uint32_t smem_u32(const void* p) {
    return (uint32_t)__cvta_generic_to_shared(p);
}
__device__ __forceinline__ void ldsm_x4(uint32_t a, uint32_t& r0, uint32_t& r1,
                                        uint32_t& r2, uint32_t& r3) {
    asm volatile("ldmatrix.sync.aligned.m8n8.x4.shared.b16 {%0,%1,%2,%3}, [%4];\n"
                 : "=r"(r0), "=r"(r1), "=r"(r2), "=r"(r3) : "r"(a));
}
__device__ __forceinline__ void ldsm_x4t(uint32_t a, uint32_t& r0, uint32_t& r1,
                                         uint32_t& r2, uint32_t& r3) {
    asm volatile("ldmatrix.sync.aligned.m8n8.x4.trans.shared.b16 {%0,%1,%2,%3}, [%4];\n"
                 : "=r"(r0), "=r"(r1), "=r"(r2), "=r"(r3) : "r"(a));
}
__device__ __forceinline__ void mma16816(float& d0, float& d1, float& d2, float& d3,
                                         uint32_t a0, uint32_t a1, uint32_t a2,
                                         uint32_t a3, uint32_t b0, uint32_t b1) {
    asm volatile(
        "mma.sync.aligned.m16n8k16.row.col.f32.bf16.bf16.f32 "
        "{%0,%1,%2,%3},{%4,%5,%6,%7},{%8,%9},{%0,%1,%2,%3};\n"
        : "+f"(d0), "+f"(d1), "+f"(d2), "+f"(d3)
        : "r"(a0), "r"(a1), "r"(a2), "r"(a3), "r"(b0), "r"(b1));
}
__device__ __forceinline__ float gelu_fast(float v) {
    float u = v * (0.7978845608f + 0.0356774081f * v * v);
    float th;
    asm("tanh.approx.f32 %0, %1;\n" : "=f"(th) : "f"(u));
    return 0.5f * v * (1.0f + th);
}

// LayerNorm fp32 xs -> bf16 h (stride 72). 4 threads/row, vectorized loads.
__device__ __forceinline__ void layernorm_bf16(const float* __restrict__ xs,
                                               const float* __restrict__ g,
                                               const float* __restrict__ b,
                                               __nv_bfloat16* __restrict__ h, int tid) {
    const int row = tid >> 2;
    const int c0 = (tid & 3) * 16;
    const float4* src = (const float4*)(xs + row * 64 + c0);
    float4 v4[4];
    float s = 0.f, s2 = 0.f;
    #pragma unroll
    for (int i = 0; i < 4; ++i) {
        v4[i] = src[i];
        s += v4[i].x + v4[i].y + v4[i].z + v4[i].w;
        s2 += v4[i].x * v4[i].x + v4[i].y * v4[i].y
            + v4[i].z * v4[i].z + v4[i].w * v4[i].w;
    }
    s  += __shfl_xor_sync(0xffffffffu, s, 1);
    s2 += __shfl_xor_sync(0xffffffffu, s2, 1);
    s  += __shfl_xor_sync(0xffffffffu, s, 2);
    s2 += __shfl_xor_sync(0xffffffffu, s2, 2);
    const float mu = s * (1.0f / 64.0f);
    const float var = s2 * (1.0f / 64.0f) - mu * mu;
    const float rstd = rsqrtf(var + EPS_);
    const float* v = (const float*)v4;
    #pragma unroll
    for (int i = 0; i < 8; ++i) {
        const float h0 = (v[2 * i] - mu) * rstd * g[c0 + 2 * i] + b[c0 + 2 * i];
        const float h1 = (v[2 * i + 1] - mu) * rstd * g[c0 + 2 * i + 1] + b[c0 + 2 * i + 1];
        *(uint32_t*)(h + row * 72 + c0 + 2 * i) = packbf(h0, h1);
    }
}

// smem: xs fp32 16384 | hb bf16 64x72 9216 | act bf16 (qkv 64x200 / fc 64x264)
#define OFF_XS 0
#define OFF_HB 16384
#define OFF_ACT 25600
#define SMEM_BYTES (25600 + 64 * 264 * 2)   // 59392

__global__ __launch_bounds__(256, 3) void block_tc_kernel(
    const float* __restrict__ x,
    const float* __restrict__ ln1_g, const float* __restrict__ ln1_b,
    const float* __restrict__ qkv_b,
    const float* __restrict__ aproj_b,
    const float* __restrict__ ln2_g, const float* __restrict__ ln2_b,
    const float* __restrict__ fc_b,
    const float* __restrict__ mproj_b,
    float* __restrict__ out) {
    extern __shared__ char smem[];
    float* xs = (float*)(smem + OFF_XS);
    __nv_bfloat16* hb = (__nv_bfloat16*)(smem + OFF_HB);      // stride 72
    __nv_bfloat16* qkvs = (__nv_bfloat16*)(smem + OFF_ACT);   // stride 200 / 264
    const uint32_t hb_a = smem_u32(hb);
    const uint32_t act_a = smem_u32(qkvs);

    const int tid = threadIdx.x;
    const int wid = tid >> 5;
    const int lane = tid & 31;
    const int g = lane >> 2;
    const int t = lane & 3;
    const int lr = lane & 15;             // ldsm row-in-tile
    const int lc = (lane >> 4) << 3;      // ldsm col offset
    const int mg = wid & 1;               // 2m x 2n partition (aproj/mproj)
    const int ng = wid >> 1;

    const size_t base = (size_t)blockIdx.x * (T_ * C_);
    const float* xg = x + base;
    float* og = out + base;

    // ---- load x ----
    {
        const float4* src = (const float4*)xg;
        float4* dst = (float4*)xs;
        #pragma unroll
        for (int i = tid; i < T_ * C_ / 4; i += 256) dst[i] = src[i];
    }
    __syncthreads();

    // ---- LN1 -> hb ----
    layernorm_bf16(xs, ln1_g, ln1_b, hb, tid);
    __syncthreads();

    // ---- QKV: warp owns cols [24w, 24w+24), loops all 4 m-tiles ----
    {
        uint2 B[4][3];
        #pragma unroll
        for (int kt = 0; kt < 4; ++kt)
            #pragma unroll
            for (int j = 0; j < 3; ++j)
                B[kt][j] = __ldg(g_fqkv + ((kt * 24 + wid * 3 + j) << 5) + lane);
        float2 bias[3];
        #pragma unroll
        for (int j = 0; j < 3; ++j)
            bias[j] = *(const float2*)(qkv_b + (wid * 3 + j) * 8 + t * 2);
        #pragma unroll
        for (int mt = 0; mt < 4; ++mt) {
            float d[3][4];
            #pragma unroll
            for (int j = 0; j < 3; ++j) {
                d[j][0] = d[j][2] = bias[j].x;
                d[j][1] = d[j][3] = bias[j].y;
            }
            #pragma unroll
            for (int kt = 0; kt < 4; ++kt) {
                uint32_t a0, a1, a2, a3;
                ldsm_x4(hb_a + (uint32_t)(((mt * 16 + lr) * 72 + kt * 16 + lc) * 2),
                        a0, a1, a2, a3);
                #pragma unroll
                for (int j = 0; j < 3; ++j)
                    mma16816(d[j][0], d[j][1], d[j][2], d[j][3],
                             a0, a1, a2, a3, B[kt][j].x, B[kt][j].y);
            }
            const int rr0 = mt * 16 + g, rr1 = rr0 + 8;
            #pragma unroll
            for (int j = 0; j < 3; ++j) {
                const int col = (wid * 3 + j) * 8 + t * 2;
                *(uint32_t*)(qkvs + rr0 * 200 + col) = packbf(d[j][0], d[j][1]);
                *(uint32_t*)(qkvs + rr1 * 200 + col) = packbf(d[j][2], d[j][3]);
            }
        }
    }
    __syncthreads();

    // ---- attention (tensor cores, register softmax) ----
    {
        const int h = wid >> 1;
        const int half = wid & 1;
        #pragma unroll
        for (int mt = 0; mt < 2; ++mt) {
            const int rowbase = half * 32 + mt * 16;
            uint32_t qa0, qa1, qa2, qa3;
            ldsm_x4(act_a + (uint32_t)(((rowbase + lr) * 200 + h * 16 + lc) * 2),
                    qa0, qa1, qa2, qa3);
            // S = Q K^T : 4x ldsm_x4 loads b-frags for j-pairs
            float s[8][4];
            #pragma unroll
            for (int jp = 0; jp < 4; ++jp) {
                const int kr = jp * 16 + ((lane & 16) >> 1) + (lane & 7);
                const int kc = 64 + h * 16 + (lane & 8);
                uint32_t kb0, kb1, kb2, kb3;
                ldsm_x4(act_a + (uint32_t)((kr * 200 + kc) * 2), kb0, kb1, kb2, kb3);
                s[2 * jp][0] = s[2 * jp][1] = s[2 * jp][2] = s[2 * jp][3] = 0.f;
                s[2 * jp + 1][0] = s[2 * jp + 1][1] = s[2 * jp + 1][2] = s[2 * jp + 1][3] = 0.f;
                mma16816(s[2 * jp][0], s[2 * jp][1], s[2 * jp][2], s[2 * jp][3],
                         qa0, qa1, qa2, qa3, kb0, kb1);
                mma16816(s[2 * jp + 1][0], s[2 * jp + 1][1], s[2 * jp + 1][2], s[2 * jp + 1][3],
                         qa0, qa1, qa2, qa3, kb2, kb3);
            }
            const int rA = rowbase + g, rB = rA + 8;
            float mA = -1e30f, mB = -1e30f;
            #pragma unroll
            for (int j = 0; j < 8; ++j) {
                #pragma unroll
                for (int e = 0; e < 2; ++e) {
                    const int col = j * 8 + t * 2 + e;
                    s[j][e]     = (col <= rA) ? s[j][e] * 0.25f     : -1e30f;
                    s[j][2 + e] = (col <= rB) ? s[j][2 + e] * 0.25f : -1e30f;
                    mA = fmaxf(mA, s[j][e]);
                    mB = fmaxf(mB, s[j][2 + e]);
                }
            }
            mA = fmaxf(mA, __shfl_xor_sync(0xffffffffu, mA, 1));
            mA = fmaxf(mA, __shfl_xor_sync(0xffffffffu, mA, 2));
            mB = fmaxf(mB, __shfl_xor_sync(0xffffffffu, mB, 1));
            mB = fmaxf(mB, __shfl_xor_sync(0xffffffffu, mB, 2));
            float sA = 0.f, sB = 0.f;
            #pragma unroll
            for (int j = 0; j < 8; ++j) {
                #pragma unroll
                for (int e = 0; e < 2; ++e) {
                    s[j][e] = __expf(s[j][e] - mA);
                    s[j][2 + e] = __expf(s[j][2 + e] - mB);
                    sA += s[j][e];
                    sB += s[j][2 + e];
                }
            }
            sA += __shfl_xor_sync(0xffffffffu, sA, 1);
            sA += __shfl_xor_sync(0xffffffffu, sA, 2);
            sB += __shfl_xor_sync(0xffffffffu, sB, 1);
            sB += __shfl_xor_sync(0xffffffffu, sB, 2);
            const float invA = 1.0f / sA, invB = 1.0f / sB;
            float y0[4] = {0.f, 0.f, 0.f, 0.f};
            float y1[4] = {0.f, 0.f, 0.f, 0.f};
            #pragma unroll
            for (int kk = 0; kk < 4; ++kk) {
                const uint32_t pa0 = packbf(s[2 * kk][0] * invA, s[2 * kk][1] * invA);
                const uint32_t pa1 = packbf(s[2 * kk][2] * invB, s[2 * kk][3] * invB);
                const uint32_t pa2 = packbf(s[2 * kk + 1][0] * invA, s[2 * kk + 1][1] * invA);
                const uint32_t pa3 = packbf(s[2 * kk + 1][2] * invB, s[2 * kk + 1][3] * invB);
                const int vr = kk * 16 + lr;
                const int vc = 128 + h * 16 + lc;
                uint32_t vb0, vb1, vb2, vb3;
                ldsm_x4t(act_a + (uint32_t)((vr * 200 + vc) * 2), vb0, vb1, vb2, vb3);
                mma16816(y0[0], y0[1], y0[2], y0[3], pa0, pa1, pa2, pa3, vb0, vb1);
                mma16816(y1[0], y1[1], y1[2], y1[3], pa0, pa1, pa2, pa3, vb2, vb3);
            }
            const int cy = h * 16 + t * 2;
            *(uint32_t*)(hb + (rowbase + g) * 72 + cy)         = packbf(y0[0], y0[1]);
            *(uint32_t*)(hb + (rowbase + g + 8) * 72 + cy)     = packbf(y0[2], y0[3]);
            *(uint32_t*)(hb + (rowbase + g) * 72 + cy + 8)     = packbf(y1[0], y1[1]);
            *(uint32_t*)(hb + (rowbase + g + 8) * 72 + cy + 8) = packbf(y1[2], y1[3]);
        }
    }
    __syncthreads();

    // ---- attention proj + residual: warp owns 2 m-tiles x 2 n-tiles ----
    {
        uint2 B[4][2];
        #pragma unroll
        for (int kt = 0; kt < 4; ++kt)
            #pragma unroll
            for (int nl = 0; nl < 2; ++nl)
                B[kt][nl] = __ldg(g_fap + ((kt * 8 + ng * 2 + nl) << 5) + lane);
        float d[2][2][4];
        #pragma unroll
        for (int nl = 0; nl < 2; ++nl) {
            const float2 bb = *(const float2*)(aproj_b + (ng * 2 + nl) * 8 + t * 2);
            #pragma unroll
            for (int ml = 0; ml < 2; ++ml) {
                d[ml][nl][0] = d[ml][nl][2] = bb.x;
                d[ml][nl][1] = d[ml][nl][3] = bb.y;
            }
        }
        #pragma unroll
        for (int kt = 0; kt < 4; ++kt) {
            uint32_t a[2][4];
            #pragma unroll
            for (int ml = 0; ml < 2; ++ml)
                ldsm_x4(hb_a + (uint32_t)((((mg * 2 + ml) * 16 + lr) * 72 + kt * 16 + lc) * 2),
                        a[ml][0], a[ml][1], a[ml][2], a[ml][3]);
            #pragma unroll
            for (int ml = 0; ml < 2; ++ml)
                #pragma unroll
                for (int nl = 0; nl < 2; ++nl)
                    mma16816(d[ml][nl][0], d[ml][nl][1], d[ml][nl][2], d[ml][nl][3],
                             a[ml][0], a[ml][1], a[ml][2], a[ml][3],
                             B[kt][nl].x, B[kt][nl].y);
        }
        #pragma unroll
        for (int ml = 0; ml < 2; ++ml) {
            const int rr0 = (mg * 2 + ml) * 16 + g, rr1 = rr0 + 8;
            #pragma unroll
            for (int nl = 0; nl < 2; ++nl) {
                const int col = (ng * 2 + nl) * 8 + t * 2;
                float2 v0 = *(float2*)(xs + rr0 * 64 + col);
                float2 v1 = *(float2*)(xs + rr1 * 64 + col);
                v0.x += d[ml][nl][0]; v0.y += d[ml][nl][1];
                v1.x += d[ml][nl][2]; v1.y += d[ml][nl][3];
                *(float2*)(xs + rr0 * 64 + col) = v0;
                *(float2*)(xs + rr1 * 64 + col) = v1;
            }
        }
    }
    __syncthreads();

    // ---- LN2 -> hb ----
    layernorm_bf16(xs, ln2_g, ln2_b, hb, tid);

    // ---- MLP output accumulator init: mproj_b + residual (2m x 2n) ----
    float accO[2][2][4];
    #pragma unroll
    for (int nl = 0; nl < 2; ++nl) {
        const int col = (ng * 2 + nl) * 8 + t * 2;
        const float2 bb = *(const float2*)(mproj_b + col);
        #pragma unroll
        for (int ml = 0; ml < 2; ++ml) {
            const int rr0 = (mg * 2 + ml) * 16 + g;
            const float2 x0 = *(const float2*)(xs + rr0 * 64 + col);
            const float2 x1 = *(const float2*)(xs + (rr0 + 8) * 64 + col);
            accO[ml][nl][0] = bb.x + x0.x; accO[ml][nl][1] = bb.y + x0.y;
            accO[ml][nl][2] = bb.x + x1.x; accO[ml][nl][3] = bb.y + x1.y;
        }
    }
    __syncthreads();

    // ---- FC + GELU: warp owns cols [32w, 32w+32) of 256 -> fcact (stride 264)
    __nv_bfloat16* fcact = qkvs;
    {
        uint2 B[4][4];
        #pragma unroll
        for (int kt = 0; kt < 4; ++kt)
            #pragma unroll
            for (int j = 0; j < 4; ++j)
                B[kt][j] = __ldg(g_ffc + ((kt * 32 + wid * 4 + j) << 5) + lane);
        float2 bias[4];
        #pragma unroll
        for (int j = 0; j < 4; ++j)
            bias[j] = *(const float2*)(fc_b + (wid * 4 + j) * 8 + t * 2);
        #pragma unroll
        for (int mt = 0; mt < 4; ++mt) {
            float d[4][4];
            #pragma unroll
            for (int j = 0; j < 4; ++j) {
                d[j][0] = d[j][2] = bias[j].x;
                d[j][1] = d[j][3] = bias[j].y;
            }
            #pragma unroll
            for (int kt = 0; kt < 4; ++kt) {
                uint32_t a0, a1, a2, a3;
                ldsm_x4(hb_a + (uint32_t)(((mt * 16 + lr) * 72 + kt * 16 + lc) * 2),
                        a0, a1, a2, a3);
                #pragma unroll
                for (int j = 0; j < 4; ++j)
                    mma16816(d[j][0], d[j][1], d[j][2], d[j][3],
                             a0, a1, a2, a3, B[kt][j].x, B[kt][j].y);
            }
            const int rr0 = mt * 16 + g, rr1 = rr0 + 8;
            #pragma unroll
            for (int j = 0; j < 4; ++j) {
                const int col = (wid * 4 + j) * 8 + t * 2;
                *(uint32_t*)(fcact + rr0 * 264 + col) =
                    packbf(gelu_fast(d[j][0]), gelu_fast(d[j][1]));
                *(uint32_t*)(fcact + rr1 * 264 + col) =
                    packbf(gelu_fast(d[j][2]), gelu_fast(d[j][3]));
            }
        }
    }
    __syncthreads();

    // ---- MLP proj: K=256, warp owns 2 m-tiles x 2 n-tiles ----
    {
        #pragma unroll
        for (int kt = 0; kt < 16; ++kt) {
            const uint2 b0 = __ldg(g_fmp + ((kt * 8 + ng * 2) << 5) + lane);
            const uint2 b1 = __ldg(g_fmp + ((kt * 8 + ng * 2 + 1) << 5) + lane);
            uint32_t a[2][4];
            #pragma unroll
            for (int ml = 0; ml < 2; ++ml)
                ldsm_x4(act_a + (uint32_t)((((mg * 2 + ml) * 16 + lr) * 264 + kt * 16 + lc) * 2),
                        a[ml][0], a[ml][1], a[ml][2], a[ml][3]);
            #pragma unroll
            for (int ml = 0; ml < 2; ++ml) {
                mma16816(accO[ml][0][0], accO[ml][0][1], accO[ml][0][2], accO[ml][0][3],
                         a[ml][0], a[ml][1], a[ml][2], a[ml][3], b0.x, b0.y);
                mma16816(accO[ml][1][0], accO[ml][1][1], accO[ml][1][2], accO[ml][1][3],
                         a[ml][0], a[ml][1], a[ml][2], a[ml][3], b1.x, b1.y);
            }
        }
    }

    // ---- store output ----
    #pragma unroll
    for (int ml = 0; ml < 2; ++ml) {
        const int rr0 = (mg * 2 + ml) * 16 + g, rr1 = rr0 + 8;
        #pragma unroll
        for (int nl = 0; nl < 2; ++nl) {
            const int col = (ng * 2 + nl) * 8 + t * 2;
            *(float2*)(og + rr0 * 64 + col) = make_float2(accO[ml][nl][0], accO[ml][nl][1]);
            *(float2*)(og + rr1 * 64 + col) = make_float2(accO[ml][nl][2], accO[ml][nl][3]);
        }
    }
}

extern "C" void kernel_launch(void* const* d_in, const int* in_sizes, int n_in,
                              void* d_out, int out_size) {
    const float* x       = (const float*)d_in[0];
    const float* ln1_g   = (const float*)d_in[1];
    const float* ln1_b   = (const float*)d_in[2];
    const float* qkv_w   = (const float*)d_in[3];
    const float* qkv_b   = (const float*)d_in[4];
    const float* aproj_w = (const float*)d_in[5];
    const float* aproj_b = (const float*)d_in[6];
    const float* ln2_g   = (const float*)d_in[7];
    const float* ln2_b   = (const float*)d_in[8];
    const float* fc_w    = (const float*)d_in[9];
    const float* fc_b    = (const float*)d_in[10];
    const float* mproj_w = (const float*)d_in[11];
    const float* mproj_b = (const float*)d_in[12];
    float* out = (float*)d_out;

    const int B = in_sizes[0] / (T_ * C_);

    convert_weights_kernel<<<16, 256>>>(qkv_w, aproj_w, fc_w, mproj_w);

    cudaFuncSetAttribute(block_tc_kernel,
                         cudaFuncAttributeMaxDynamicSharedMemorySize, SMEM_BYTES);
    block_tc_kernel<<<B, 256, SMEM_BYTES>>>(
        x, ln1_g, ln1_b, qkv_b, aproj_b, ln2_g, ln2_b, fc_b, mproj_b, out);
}